// round 6
// baseline (speedup 1.0000x reference)
#include <cuda_runtime.h>
#include <cuda_bf16.h>
#include <cstdint>
#include <math.h>

// Problem constants
#define B   32
#define S   512
#define H   1024
#define T   37
#define LP  39
#define BS  (B*S)          // 16384
#define ZK2 2112           // 1024 (h) + 1024 (h*aware) + 64 (attn pad)

// Scratch (device-global)
__device__ __align__(256) __nv_bfloat16 g_Zb[BS * ZK2];  // 66 MiB
__device__ __align__(256) __nv_bfloat16 g_Wt[H * ZK2];   // [n][k]  4.3 MiB
__device__ __align__(256) float g_Y[BS * H];             // 64 MiB

// ===========================================================================
// helpers
// ===========================================================================
__device__ __forceinline__ uint32_t smem_u32(const void* p) {
    uint32_t a;
    asm("{ .reg .u64 t; cvta.to.shared.u64 t, %1; cvt.u32.u64 %0, t; }"
        : "=r"(a) : "l"(p));
    return a;
}
__device__ __forceinline__ void cp16(uint32_t dst, const void* src) {
    asm volatile("cp.async.cg.shared.global [%0], [%1], 16;\n" :: "r"(dst), "l"(src));
}
#define CP_COMMIT() asm volatile("cp.async.commit_group;\n" ::: "memory")
#define CP_WAIT(n)  asm volatile("cp.async.wait_group %0;\n" :: "n"(n) : "memory")

__device__ __forceinline__ float gelu(float v) {
    return 0.5f * v * (1.f + erff(v * 0.70710678118654752f));
}
__device__ __forceinline__ void ldsm4(uint32_t* r, uint32_t addr) {
    asm volatile("ldmatrix.sync.aligned.m8n8.x4.shared.b16 {%0,%1,%2,%3}, [%4];"
        : "=r"(r[0]), "=r"(r[1]), "=r"(r[2]), "=r"(r[3]) : "r"(addr));
}
__device__ __forceinline__ void mma_bf16(
    float* d, const uint32_t* a, uint32_t b0, uint32_t b1)
{
    asm volatile(
        "mma.sync.aligned.m16n8k16.row.col.f32.bf16.bf16.f32 "
        "{%0,%1,%2,%3}, {%4,%5,%6,%7}, {%8,%9}, {%0,%1,%2,%3};"
        : "+f"(d[0]), "+f"(d[1]), "+f"(d[2]), "+f"(d[3])
        : "r"(a[0]), "r"(a[1]), "r"(a[2]), "r"(a[3]), "r"(b0), "r"(b1));
}
// order-preserving f32 -> u32 -> warp max -> f32 (single redux, no shfl chain)
__device__ __forceinline__ float rmax32(float x) {
    uint32_t k = __float_as_uint(x);
    k = (k & 0x80000000u) ? ~k : (k | 0x80000000u);
    k = __reduce_max_sync(0xFFFFFFFFu, k);
    return __uint_as_float((k & 0x80000000u) ? (k & 0x7FFFFFFFu) : ~k);
}
__device__ __forceinline__ uint2 pack4bf(float4 v) {
    __nv_bfloat162 p0; p0.x = __float2bfloat16(v.x); p0.y = __float2bfloat16(v.y);
    __nv_bfloat162 p1; p1.x = __float2bfloat16(v.z); p1.y = __float2bfloat16(v.w);
    uint2 r; r.x = *(uint32_t*)&p0; r.y = *(uint32_t*)&p1; return r;
}

// ---------------------------------------------------------------------------
// k0: g_Wt[n][k] = bf16(W_cat[src(k)][n]) for k<2048 (src skips W2 block)
// ---------------------------------------------------------------------------
__global__ __launch_bounds__(256) void k0_transpose(const float* __restrict__ W)
{
    __shared__ float tile[32][33];
    int k0 = blockIdx.x * 32, n0 = blockIdx.y * 32;
    int tx = threadIdx.x, ty = threadIdx.y;
    #pragma unroll
    for (int j = 0; j < 32; j += 8) {
        int k = k0 + ty + j;
        int src = (k < H) ? k : (k + H);
        tile[ty + j][tx] = W[(size_t)src * H + n0 + tx];
    }
    __syncthreads();
    #pragma unroll
    for (int j = 0; j < 32; j += 8) {
        int n = n0 + ty + j;
        g_Wt[(size_t)n * ZK2 + k0 + tx] = __float2bfloat16(tile[tx][ty + j]);
    }
}

// ---------------------------------------------------------------------------
// kzero: zero pad columns [2085, 2112) of g_Wt
// ---------------------------------------------------------------------------
__global__ __launch_bounds__(256) void kzero()
{
    int idx = blockIdx.x * 256 + threadIdx.x;
    if (idx < H * 27) {
        int n = idx / 27, c = idx % 27;
        g_Wt[(size_t)n * ZK2 + 2085 + c] = __float2bfloat16(0.f);
    }
}

// ---------------------------------------------------------------------------
// k_bw2: g_Wt[n][2048+t] = bf16( sum_k bio[t][k] * W_cat[1024+k][n] )
// One block per 32 n-columns computes ALL t -> W2 read exactly once.
// ---------------------------------------------------------------------------
__global__ __launch_bounds__(256) void k_bw2(
    const float* __restrict__ bio, const float* __restrict__ W)
{
    extern __shared__ float bioS[];   // [T][H]
    int tid = threadIdx.x;
    for (int i = tid; i < T*H/4; i += 256)
        ((float4*)bioS)[i] = ((const float4*)bio)[i];
    __syncthreads();

    int n = blockIdx.x * 32 + (tid & 31);
    int th = tid >> 5;
    float acc[5] = {0.f, 0.f, 0.f, 0.f, 0.f};
    #pragma unroll 4
    for (int k = 0; k < H; k++) {
        float w = W[(size_t)(H + k) * H + n];
        #pragma unroll
        for (int j = 0; j < 5; j++) {
            int t = th + 8*j;
            float bv = (t < T) ? bioS[t*H + k] : 0.f;
            acc[j] += bv * w;
        }
    }
    #pragma unroll
    for (int j = 0; j < 5; j++) {
        int t = th + 8*j;
        if (t < T) g_Wt[(size_t)n * ZK2 + 2048 + t] = __float2bfloat16(acc[j]);
    }
}

// ---------------------------------------------------------------------------
// k1: 2 rows per warp, bf16 bio tile in smem.
// scores -> softmax -> aware; Z = bf16[h | h*aware | attn]
// ---------------------------------------------------------------------------
__global__ __launch_bounds__(256, 2) void k1_bio_attn(
    const float* __restrict__ h, const float* __restrict__ bio)
{
    extern __shared__ __align__(16) __nv_bfloat16 bioB[];   // [T][H] bf16
    int tid = threadIdx.x;
    for (int i = tid; i < T*H/2; i += 256) {
        float2 v = ((const float2*)bio)[i];
        __nv_bfloat162 p; p.x = __float2bfloat16(v.x); p.y = __float2bfloat16(v.y);
        ((__nv_bfloat162*)bioB)[i] = p;
    }
    __syncthreads();

    int wid = tid >> 5, l = tid & 31;
    int row0 = (blockIdx.x * 8 + wid) * 2;
    int row1 = row0 + 1;
    const uint2* bB = (const uint2*)bioB;   // 4 bf16 per entry, row stride 256

    // ---- phase A: scores (both rows share each bio read) ----
    float v0a = -1e30f, v0b = -1e30f, v1a = -1e30f, v1b = -1e30f;
    {
        float4 h0[8], h1[8];
        const float4* p0 = (const float4*)(h + (size_t)row0 * H);
        const float4* p1 = (const float4*)(h + (size_t)row1 * H);
        #pragma unroll
        for (int j = 0; j < 8; j++) { h0[j] = p0[j*32 + l]; h1[j] = p1[j*32 + l]; }

        for (int t = 0; t < T; t++) {
            const uint2* bt = bB + t*256;
            float s0 = 0.f, s1 = 0.f;
            #pragma unroll
            for (int j = 0; j < 8; j++) {
                uint2 pk = bt[j*32 + l];
                float2 f01 = __bfloat1622float2(*(__nv_bfloat162*)&pk.x);
                float2 f23 = __bfloat1622float2(*(__nv_bfloat162*)&pk.y);
                s0 += h0[j].x*f01.x + h0[j].y*f01.y + h0[j].z*f23.x + h0[j].w*f23.y;
                s1 += h1[j].x*f01.x + h1[j].y*f01.y + h1[j].z*f23.x + h1[j].w*f23.y;
            }
            #pragma unroll
            for (int o = 16; o; o >>= 1) {
                s0 += __shfl_xor_sync(~0u, s0, o);
                s1 += __shfl_xor_sync(~0u, s1, o);
            }
            s0 *= 0.03125f; s1 *= 0.03125f;
            if (t < 32) { if (l == t)    { v0a = s0; v1a = s1; } }
            else        { if (l == t-32) { v0b = s0; v1b = s1; } }
        }

        // write h-part of Z now so h regs die before phase B
        __nv_bfloat16* zr0 = g_Zb + (size_t)row0 * ZK2;
        __nv_bfloat16* zr1 = g_Zb + (size_t)row1 * ZK2;
        #pragma unroll
        for (int j = 0; j < 8; j++) {
            *(uint2*)(zr0 + j*128 + 4*l) = pack4bf(h0[j]);
            *(uint2*)(zr1 + j*128 + 4*l) = pack4bf(h1[j]);
        }
    }

    // ---- softmax (per row, in-warp) ----
    float e0a, e0b, e1a, e1b;
    {
        float m0 = rmax32(fmaxf(v0a, (l < T-32) ? v0b : -1e30f));
        e0a = __expf(v0a - m0);
        e0b = (l < T-32) ? __expf(v0b - m0) : 0.f;
        float ss = e0a + e0b;
        #pragma unroll
        for (int o = 16; o; o >>= 1) ss += __shfl_xor_sync(~0u, ss, o);
        float inv = 1.f / ss; e0a *= inv; e0b *= inv;

        float m1 = rmax32(fmaxf(v1a, (l < T-32) ? v1b : -1e30f));
        e1a = __expf(v1a - m1);
        e1b = (l < T-32) ? __expf(v1b - m1) : 0.f;
        float s1s = e1a + e1b;
        #pragma unroll
        for (int o = 16; o; o >>= 1) s1s += __shfl_xor_sync(~0u, s1s, o);
        float inv1 = 1.f / s1s; e1a *= inv1; e1b *= inv1;
    }

    // attn columns [2048, 2112): each lane writes 2 bf16 per row
    {
        __nv_bfloat16* zr0 = g_Zb + (size_t)row0 * ZK2;
        __nv_bfloat16* zr1 = g_Zb + (size_t)row1 * ZK2;
        int i0 = 2*l, i1 = 2*l + 1;
        float r0lo0 = __shfl_sync(~0u, e0a, i0 & 31);
        float r0hi0 = __shfl_sync(~0u, e0b, (i0 >= 32) ? (i0 - 32) : 0);
        float r0lo1 = __shfl_sync(~0u, e0a, i1 & 31);
        float r0hi1 = __shfl_sync(~0u, e0b, (i1 >= 32) ? (i1 - 32) : 0);
        float r1lo0 = __shfl_sync(~0u, e1a, i0 & 31);
        float r1hi0 = __shfl_sync(~0u, e1b, (i0 >= 32) ? (i0 - 32) : 0);
        float r1lo1 = __shfl_sync(~0u, e1a, i1 & 31);
        float r1hi1 = __shfl_sync(~0u, e1b, (i1 >= 32) ? (i1 - 32) : 0);
        float a00 = (i0 < 32) ? r0lo0 : r0hi0; if (i0 >= T) a00 = 0.f;
        float a01 = (i1 < 32) ? r0lo1 : r0hi1; if (i1 >= T) a01 = 0.f;
        float a10 = (i0 < 32) ? r1lo0 : r1hi0; if (i0 >= T) a10 = 0.f;
        float a11 = (i1 < 32) ? r1lo1 : r1hi1; if (i1 >= T) a11 = 0.f;
        __nv_bfloat162 q0; q0.x = __float2bfloat16(a00); q0.y = __float2bfloat16(a01);
        __nv_bfloat162 q1; q1.x = __float2bfloat16(a10); q1.y = __float2bfloat16(a11);
        *(uint32_t*)(zr0 + 2048 + 2*l) = *(uint32_t*)&q0;
        *(uint32_t*)(zr1 + 2048 + 2*l) = *(uint32_t*)&q1;
    }

    // ---- phase B: aware accumulation ----
    float4 aw0[8], aw1[8];
    #pragma unroll
    for (int j = 0; j < 8; j++) {
        aw0[j] = make_float4(0.f,0.f,0.f,0.f);
        aw1[j] = make_float4(0.f,0.f,0.f,0.f);
    }
    for (int t = 0; t < T; t++) {
        float a0 = (t < 32) ? __shfl_sync(~0u, e0a, t) : __shfl_sync(~0u, e0b, t - 32);
        float a1 = (t < 32) ? __shfl_sync(~0u, e1a, t) : __shfl_sync(~0u, e1b, t - 32);
        const uint2* bt = bB + t*256;
        #pragma unroll
        for (int j = 0; j < 8; j++) {
            uint2 pk = bt[j*32 + l];
            float2 f01 = __bfloat1622float2(*(__nv_bfloat162*)&pk.x);
            float2 f23 = __bfloat1622float2(*(__nv_bfloat162*)&pk.y);
            aw0[j].x += a0*f01.x; aw0[j].y += a0*f01.y;
            aw0[j].z += a0*f23.x; aw0[j].w += a0*f23.y;
            aw1[j].x += a1*f01.x; aw1[j].y += a1*f01.y;
            aw1[j].z += a1*f23.x; aw1[j].w += a1*f23.y;
        }
    }

    // product write: reload h (L2-hot)
    {
        __nv_bfloat16* zr0 = g_Zb + (size_t)row0 * ZK2;
        __nv_bfloat16* zr1 = g_Zb + (size_t)row1 * ZK2;
        const float4* p0 = (const float4*)(h + (size_t)row0 * H);
        const float4* p1 = (const float4*)(h + (size_t)row1 * H);
        #pragma unroll
        for (int j = 0; j < 8; j++) {
            float4 hv = p0[j*32 + l];
            float4 pr = make_float4(hv.x*aw0[j].x, hv.y*aw0[j].y, hv.z*aw0[j].z, hv.w*aw0[j].w);
            *(uint2*)(zr0 + 1024 + j*128 + 4*l) = pack4bf(pr);
            hv = p1[j*32 + l];
            pr = make_float4(hv.x*aw1[j].x, hv.y*aw1[j].y, hv.z*aw1[j].z, hv.w*aw1[j].w);
            *(uint2*)(zr1 + 1024 + j*128 + 4*l) = pack4bf(pr);
        }
    }
}

// ---------------------------------------------------------------------------
// k2: Y = gelu(Z @ Wt^T + bc)  bf16 mma.m16n8k16, BM=128 BN=128 BK=64,
// 3-stage cp.async, SW128 swizzle + ldmatrix, 8 warps (4x2), 2 CTAs/SM.
// ---------------------------------------------------------------------------
#define KBM 128
#define KBN 128
#define KBK 64
#define NKI (ZK2/KBK)            // 33
#define STG (KBM*128 + KBN*128)  // 32768 bytes
#define SMEM_K2 (3*STG)          // 98304

__device__ __forceinline__ void k2_load_stage(
    uint32_t sb, int tid, int j, const char* Zb, const char* Wb)
{
    uint32_t base = sb + (j % 3) * STG;
    int kb = j * 128;
    #pragma unroll
    for (int q = 0; q < 8; q++) {
        int idx = tid + 256*q;
        if (q < 4) {
            int m = idx >> 3, c = idx & 7;
            cp16(base + ((m*128 + c*16) ^ ((m & 7) << 4)),
                 Zb + (size_t)m * (ZK2*2) + kb + c*16);
        } else {
            int ci = idx - 1024;
            int n = ci >> 3, c = ci & 7;
            cp16(base + 16384 + ((n*128 + c*16) ^ ((n & 7) << 4)),
                 Wb + (size_t)n * (ZK2*2) + kb + c*16);
        }
    }
}

__global__ __launch_bounds__(256, 2) void k2_mma(const float* __restrict__ bc)
{
    extern __shared__ __align__(16) char smem[];
    uint32_t sb = smem_u32(smem);
    int tid = threadIdx.x, lane = tid & 31, wid = tid >> 5;
    int wm = wid & 3, wn = wid >> 2;
    int row0 = blockIdx.y * KBM, n0 = blockIdx.x * KBN;

    const char* Zb = (const char*)g_Zb + (size_t)row0 * (ZK2*2);
    const char* Wb = (const char*)g_Wt + (size_t)n0   * (ZK2*2);

    float acc[2][8][4];
    #pragma unroll
    for (int mt = 0; mt < 2; mt++)
        #pragma unroll
        for (int nt = 0; nt < 8; nt++)
            #pragma unroll
            for (int q = 0; q < 4; q++) acc[mt][nt][q] = 0.f;

    k2_load_stage(sb, tid, 0, Zb, Wb); CP_COMMIT();
    k2_load_stage(sb, tid, 1, Zb, Wb); CP_COMMIT();

    int r15 = lane & 15;
    int hb  = (lane >> 4) << 4;

    for (int i = 0; i < NKI; i++) {
        int j = i + 2;
        if (j < NKI) k2_load_stage(sb, tid, j, Zb, Wb);
        CP_COMMIT();
        CP_WAIT(2);
        __syncthreads();

        uint32_t Ab = sb + (i % 3) * STG;
        uint32_t Bb = Ab + 16384;
        #pragma unroll
        for (int kk = 0; kk < 4; kk++) {
            int kbyte = kk*32 + hb;
            uint32_t a[2][4];
            #pragma unroll
            for (int mt = 0; mt < 2; mt++) {
                int rr = wm*32 + mt*16 + r15;
                ldsm4(a[mt], Ab + rr*128 + (kbyte ^ ((rr & 7) << 4)));
            }
            #pragma unroll
            for (int ntp = 0; ntp < 4; ntp++) {
                int nr = wn*64 + ntp*16 + r15;
                uint32_t b[4];
                ldsm4(b, Bb + nr*128 + (kbyte ^ ((nr & 7) << 4)));
                #pragma unroll
                for (int mt = 0; mt < 2; mt++) {
                    mma_bf16(acc[mt][2*ntp],   a[mt], b[0], b[2]);
                    mma_bf16(acc[mt][2*ntp+1], a[mt], b[1], b[3]);
                }
            }
        }
        __syncthreads();
    }

    int g = lane >> 2, t4 = lane & 3;
    #pragma unroll
    for (int mt = 0; mt < 2; mt++) {
        #pragma unroll
        for (int nt = 0; nt < 8; nt++) {
            int r0 = row0 + wm*32 + mt*16 + g;
            int c  = n0 + wn*64 + nt*8 + 2*t4;
            float b0v = __ldg(bc + c), b1v = __ldg(bc + c + 1);
            float2 o0 = {gelu(acc[mt][nt][0] + b0v), gelu(acc[mt][nt][1] + b1v)};
            float2 o1 = {gelu(acc[mt][nt][2] + b0v), gelu(acc[mt][nt][3] + b1v)};
            *(float2*)(g_Y + (size_t)r0 * H + c) = o0;
            *(float2*)(g_Y + (size_t)(r0 + 8) * H + c) = o1;
        }
    }
}

// ---------------------------------------------------------------------------
// k3: logits = Y @ W_crf + b_crf -> ner_scores (+ pads). 2 rows/warp,
// bf16 W_crf tile in smem (halves crossbar traffic).
// ---------------------------------------------------------------------------
__global__ __launch_bounds__(256, 2) void k3_crf_proj(
    const float* __restrict__ Wc, const float* __restrict__ bcrf,
    float* __restrict__ out)
{
    extern __shared__ __align__(16) __nv_bfloat16 Ws[];   // [T][H] bf16
    int tid = threadIdx.x;
    for (int idx = tid; idx < H*T; idx += 256) {
        int t = idx / H, k = idx % H;          // consecutive k -> conflict-free stores
        Ws[t*H + k] = __float2bfloat16(Wc[(size_t)k * T + t]);
    }
    __syncthreads();

    int wid = tid >> 5, l = tid & 31;
    int row0 = (blockIdx.x * 8 + wid) * 2;
    int row1 = row0 + 1;
    const uint2* wB = (const uint2*)Ws;

    float4 y0[8], y1[8];
    const float4* p0 = (const float4*)(g_Y + (size_t)row0 * H);
    const float4* p1 = (const float4*)(g_Y + (size_t)row1 * H);
    #pragma unroll
    for (int j = 0; j < 8; j++) { y0[j] = p0[j*32 + l]; y1[j] = p1[j*32 + l]; }

    float* o0 = out + (size_t)row0 * LP;
    float* o1 = out + (size_t)row1 * LP;
    for (int t = 0; t < T; t++) {
        const uint2* wt = wB + t*256;
        float s0 = 0.f, s1 = 0.f;
        #pragma unroll
        for (int j = 0; j < 8; j++) {
            uint2 pk = wt[j*32 + l];
            float2 f01 = __bfloat1622float2(*(__nv_bfloat162*)&pk.x);
            float2 f23 = __bfloat1622float2(*(__nv_bfloat162*)&pk.y);
            s0 += y0[j].x*f01.x + y0[j].y*f01.y + y0[j].z*f23.x + y0[j].w*f23.y;
            s1 += y1[j].x*f01.x + y1[j].y*f01.y + y1[j].z*f23.x + y1[j].w*f23.y;
        }
        #pragma unroll
        for (int o = 16; o; o >>= 1) {
            s0 += __shfl_xor_sync(~0u, s0, o);
            s1 += __shfl_xor_sync(~0u, s1, o);
        }
        if (l == 0) {
            float bv = __ldg(bcrf + t);
            o0[t] = s0 + bv;
            o1[t] = s1 + bv;
        }
    }
    if (l < 2) { o0[37 + l] = -10000.f; o1[37 + l] = -10000.f; }
}

// ---------------------------------------------------------------------------
// k4: CRF loglik. One warp per batch; shuffle scan, redux-based max.
// ---------------------------------------------------------------------------
__global__ __launch_bounds__(32) void k4_crf(
    const float* __restrict__ scores, const int* __restrict__ labels,
    const int* __restrict__ lens, const float* __restrict__ trans,
    float* __restrict__ loss)
{
    extern __shared__ float sc[];   // S*LP floats
    int b = blockIdx.x;
    int lane = threadIdx.x;
    int len = lens[b];
    const int* lab = labels + b*S;

    {
        uint32_t sbase = smem_u32(sc);
        const float4* src = (const float4*)(scores + (size_t)b * S * LP);
        for (int i = lane; i < S*LP/4; i += 32)
            cp16(sbase + i*16, src + i);
        CP_COMMIT();
        CP_WAIT(0);
        __syncwarp();
    }

    float ET0[LP], ET1[LP], maxT0 = -1e30f, maxT1 = -1e30f;
    {
        const float* tr = trans + lane*LP;
        #pragma unroll
        for (int f = 0; f < LP; f++) maxT0 = fmaxf(maxT0, tr[f]);
        #pragma unroll
        for (int f = 0; f < LP; f++) ET0[f] = __expf(tr[f] - maxT0);
    }
    if (lane < LP-32) {
        const float* tr = trans + (32+lane)*LP;
        #pragma unroll
        for (int f = 0; f < LP; f++) maxT1 = fmaxf(maxT1, tr[f]);
        #pragma unroll
        for (int f = 0; f < LP; f++) ET1[f] = __expf(tr[f] - maxT1);
    }

    float g = 0.f;
    for (int s2 = lane; s2 < len; s2 += 32) g += sc[s2*LP + lab[s2]];
    for (int i = lane; i <= len; i += 32) {
        int frm = (i == 0)   ? T       : lab[i-1];
        int to  = (i == len) ? (T + 1) : lab[i];
        g += trans[to*LP + frm];
    }
    #pragma unroll
    for (int o = 16; o; o >>= 1) g += __shfl_xor_sync(~0u, g, o);

    float a0 = -100.f;
    float a1 = (lane == (T - 32)) ? 0.f : -100.f;

    for (int t = 0; t < len; t++) {
        float v = rmax32(fmaxf(a0, (lane < LP-32) ? a1 : -1e30f));
        float e0 = __expf(a0 - v);
        float e1 = (lane < LP-32) ? __expf(a1 - v) : 0.f;
        float s0a = 0.f, s0b = 0.f, s1a = 0.f, s1b = 0.f;
        #pragma unroll
        for (int f = 0; f < 32; f += 2) {
            float ea = __shfl_sync(~0u, e0, f);
            float eb = __shfl_sync(~0u, e0, f+1);
            s0a += ea*ET0[f];   s0b += eb*ET0[f+1];
            s1a += ea*ET1[f];   s1b += eb*ET1[f+1];
        }
        #pragma unroll
        for (int f = 0; f < LP-32; f++) {
            float ea = __shfl_sync(~0u, e1, f);
            s0a += ea*ET0[32+f];
            s1a += ea*ET1[32+f];
        }
        a0 = sc[t*LP + lane] + v + maxT0 + __logf(s0a + s0b);
        if (lane < LP-32)
            a1 = sc[t*LP + 32 + lane] + v + maxT1 + __logf(s1a + s1b);
    }

    a0 += trans[(T+1)*LP + lane];
    if (lane < LP-32) a1 += trans[(T+1)*LP + 32 + lane];
    float v = rmax32(fmaxf(a0, (lane < LP-32) ? a1 : -1e30f));
    float e = __expf(a0 - v) + ((lane < LP-32) ? __expf(a1 - v) : 0.f);
    #pragma unroll
    for (int o = 16; o; o >>= 1) e += __shfl_xor_sync(~0u, e, o);
    if (lane == 0) loss[b] = g - (v + logf(e));
}

// ---------------------------------------------------------------------------
extern "C" void kernel_launch(void* const* d_in, const int* in_sizes, int n_in,
                              void* d_out, int out_size)
{
    const float* h      = (const float*)d_in[0];
    const int*   lens   = (const int*)d_in[2];
    const int*   labels = (const int*)d_in[3];
    const float* bio    = (const float*)d_in[4];
    const float* W_cat  = (const float*)d_in[5];
    const float* b_cat  = (const float*)d_in[6];
    const float* W_crf  = (const float*)d_in[7];
    const float* b_crf  = (const float*)d_in[8];
    const float* trans  = (const float*)d_in[9];

    float* out = (float*)d_out;            // ner_scores [B,S,LP] then loss [B]
    float* loss = out + (size_t)B * S * LP;

    size_t smem1  = (size_t)(T*H) * sizeof(__nv_bfloat16);  // 75776
    size_t smemW2 = (size_t)(T*H) * sizeof(float);          // 151552
    size_t smem3  = (size_t)(T*H) * sizeof(__nv_bfloat16);  // 75776
    size_t smem4  = (size_t)(S*LP) * sizeof(float);         // 79872

    static int attr_done = 0;
    if (!attr_done) {
        cudaFuncSetAttribute(k1_bio_attn, cudaFuncAttributeMaxDynamicSharedMemorySize, (int)smem1);
        cudaFuncSetAttribute(k_bw2,       cudaFuncAttributeMaxDynamicSharedMemorySize, (int)smemW2);
        cudaFuncSetAttribute(k2_mma,      cudaFuncAttributeMaxDynamicSharedMemorySize, SMEM_K2);
        cudaFuncSetAttribute(k3_crf_proj, cudaFuncAttributeMaxDynamicSharedMemorySize, (int)smem3);
        cudaFuncSetAttribute(k4_crf,      cudaFuncAttributeMaxDynamicSharedMemorySize, (int)smem4);
        attr_done = 1;
    }

    k0_transpose<<<dim3(2048/32, H/32), dim3(32, 8)>>>(W_cat);
    kzero<<<(H*27 + 255)/256, 256>>>();
    k_bw2<<<32, 256, smemW2>>>(bio, W_cat);
    k1_bio_attn<<<BS/16, 256, smem1>>>(h, bio);
    k2_mma<<<dim3(H/KBN, BS/KBM), 256, SMEM_K2>>>(b_cat);
    k3_crf_proj<<<BS/16, 256, smem3>>>(W_crf, b_crf, out);
    k4_crf<<<B, 32, smem4>>>(out, labels, lens, trans, loss);
}

// round 7
// speedup vs baseline: 1.4028x; 1.4028x over previous
#include <cuda_runtime.h>
#include <cuda_bf16.h>
#include <cstdint>
#include <math.h>

// Problem constants
#define B   32
#define S   512
#define H   1024
#define T   37
#define LP  39
#define BS  (B*S)          // 16384
#define ZK2 2112           // 1024 (h) + 1024 (h*aware) + 64 (attn pad)

// Scratch (device-global)
__device__ __align__(256) __nv_bfloat16 g_Zb[BS * ZK2];  // 66 MiB
__device__ __align__(256) __nv_bfloat16 g_Wt[H * ZK2];   // [n][k]  4.3 MiB
__device__ __align__(256) __nv_bfloat16 g_Yb[BS * H];    // gelu out, bf16, 32 MiB
__device__ __align__(256) __nv_bfloat16 g_W3[64 * H];    // W_crf^T padded, bf16

// ===========================================================================
// helpers
// ===========================================================================
__device__ __forceinline__ uint32_t smem_u32(const void* p) {
    uint32_t a;
    asm("{ .reg .u64 t; cvta.to.shared.u64 t, %1; cvt.u32.u64 %0, t; }"
        : "=r"(a) : "l"(p));
    return a;
}
__device__ __forceinline__ void cp16(uint32_t dst, const void* src) {
    asm volatile("cp.async.cg.shared.global [%0], [%1], 16;\n" :: "r"(dst), "l"(src));
}
#define CP_COMMIT() asm volatile("cp.async.commit_group;\n" ::: "memory")
#define CP_WAIT(n)  asm volatile("cp.async.wait_group %0;\n" :: "n"(n) : "memory")

__device__ __forceinline__ float gelu(float v) {
    return 0.5f * v * (1.f + erff(v * 0.70710678118654752f));
}
__device__ __forceinline__ void ldsm4(uint32_t* r, uint32_t addr) {
    asm volatile("ldmatrix.sync.aligned.m8n8.x4.shared.b16 {%0,%1,%2,%3}, [%4];"
        : "=r"(r[0]), "=r"(r[1]), "=r"(r[2]), "=r"(r[3]) : "r"(addr));
}
__device__ __forceinline__ void mma_bf16(
    float* d, const uint32_t* a, uint32_t b0, uint32_t b1)
{
    asm volatile(
        "mma.sync.aligned.m16n8k16.row.col.f32.bf16.bf16.f32 "
        "{%0,%1,%2,%3}, {%4,%5,%6,%7}, {%8,%9}, {%0,%1,%2,%3};"
        : "+f"(d[0]), "+f"(d[1]), "+f"(d[2]), "+f"(d[3])
        : "r"(a[0]), "r"(a[1]), "r"(a[2]), "r"(a[3]), "r"(b0), "r"(b1));
}
__device__ __forceinline__ float rmax32(float x) {
    uint32_t k = __float_as_uint(x);
    k = (k & 0x80000000u) ? ~k : (k | 0x80000000u);
    k = __reduce_max_sync(0xFFFFFFFFu, k);
    return __uint_as_float((k & 0x80000000u) ? (k & 0x7FFFFFFFu) : ~k);
}
__device__ __forceinline__ uint2 pack4bf(float4 v) {
    __nv_bfloat162 p0; p0.x = __float2bfloat16(v.x); p0.y = __float2bfloat16(v.y);
    __nv_bfloat162 p1; p1.x = __float2bfloat16(v.z); p1.y = __float2bfloat16(v.w);
    uint2 r; r.x = *(uint32_t*)&p0; r.y = *(uint32_t*)&p1; return r;
}

// ---------------------------------------------------------------------------
// k0: g_Wt[n][k] = bf16(W_cat[src(k)][n]) for k<2048 (src skips W2 block)
// ---------------------------------------------------------------------------
__global__ __launch_bounds__(256) void k0_transpose(const float* __restrict__ W)
{
    __shared__ float tile[32][33];
    int k0 = blockIdx.x * 32, n0 = blockIdx.y * 32;
    int tx = threadIdx.x, ty = threadIdx.y;
    #pragma unroll
    for (int j = 0; j < 32; j += 8) {
        int k = k0 + ty + j;
        int src = (k < H) ? k : (k + H);
        tile[ty + j][tx] = W[(size_t)src * H + n0 + tx];
    }
    __syncthreads();
    #pragma unroll
    for (int j = 0; j < 32; j += 8) {
        int n = n0 + ty + j;
        g_Wt[(size_t)n * ZK2 + k0 + tx] = __float2bfloat16(tile[tx][ty + j]);
    }
}

// ---------------------------------------------------------------------------
// kzero: zero pad columns [2085, 2112) of g_Wt
// ---------------------------------------------------------------------------
__global__ __launch_bounds__(256) void kzero()
{
    int idx = blockIdx.x * 256 + threadIdx.x;
    if (idx < H * 27) {
        int n = idx / 27, c = idx % 27;
        g_Wt[(size_t)n * ZK2 + 2085 + c] = __float2bfloat16(0.f);
    }
}

// ---------------------------------------------------------------------------
// kw3: transpose W_crf [H][T] f32 -> g_W3 [64][H] bf16 (rows T..63 zero)
// ---------------------------------------------------------------------------
__global__ __launch_bounds__(256) void kw3(const float* __restrict__ Wc)
{
    __shared__ float tile[32][33];
    int k0 = blockIdx.x * 32, t0 = blockIdx.y * 32;
    int tx = threadIdx.x, ty = threadIdx.y;
    #pragma unroll
    for (int j = 0; j < 32; j += 8) {
        int k = k0 + ty + j, t = t0 + tx;
        tile[ty + j][tx] = (t < T) ? Wc[(size_t)k * T + t] : 0.f;
    }
    __syncthreads();
    #pragma unroll
    for (int j = 0; j < 32; j += 8) {
        int t = t0 + ty + j;
        g_W3[(size_t)t * H + k0 + tx] = __float2bfloat16(tile[tx][ty + j]);
    }
}

// ---------------------------------------------------------------------------
// k_bw2: g_Wt[n][2048+t] = bf16( sum_k bio[t][k] * W_cat[1024+k][n] )
// ---------------------------------------------------------------------------
__global__ __launch_bounds__(256) void k_bw2(
    const float* __restrict__ bio, const float* __restrict__ W)
{
    extern __shared__ float bioS[];   // [T][H]
    int tid = threadIdx.x;
    for (int i = tid; i < T*H/4; i += 256)
        ((float4*)bioS)[i] = ((const float4*)bio)[i];
    __syncthreads();

    int n = blockIdx.x * 32 + (tid & 31);
    int th = tid >> 5;
    float acc[5] = {0.f, 0.f, 0.f, 0.f, 0.f};
    #pragma unroll 4
    for (int k = 0; k < H; k++) {
        float w = W[(size_t)(H + k) * H + n];
        #pragma unroll
        for (int j = 0; j < 5; j++) {
            int t = th + 8*j;
            float bv = (t < T) ? bioS[t*H + k] : 0.f;
            acc[j] += bv * w;
        }
    }
    #pragma unroll
    for (int j = 0; j < 5; j++) {
        int t = th + 8*j;
        if (t < T) g_Wt[(size_t)n * ZK2 + 2048 + t] = __float2bfloat16(acc[j]);
    }
}

// ---------------------------------------------------------------------------
// k1: 2 rows per warp, bf16 bio tile in smem, HFMA2 bf16x2 arithmetic.
// scores -> softmax -> aware; Z = bf16[h | h*aware | attn]
// ---------------------------------------------------------------------------
__global__ __launch_bounds__(256, 2) void k1_bio_attn(
    const float* __restrict__ h, const float* __restrict__ bio)
{
    extern __shared__ __align__(16) __nv_bfloat16 bioB[];   // [T][H] bf16
    int tid = threadIdx.x;
    for (int i = tid; i < T*H/2; i += 256) {
        float2 v = ((const float2*)bio)[i];
        __nv_bfloat162 p; p.x = __float2bfloat16(v.x); p.y = __float2bfloat16(v.y);
        ((__nv_bfloat162*)bioB)[i] = p;
    }
    __syncthreads();

    int wid = tid >> 5, l = tid & 31;
    int row0 = (blockIdx.x * 8 + wid) * 2;
    int row1 = row0 + 1;
    const uint2* bB = (const uint2*)bioB;   // 4 bf16 per entry, row stride 256

    // h rows as packed bf16 (also the Z h-part payload)
    uint2 h0p[8], h1p[8];
    {
        const float4* p0 = (const float4*)(h + (size_t)row0 * H);
        const float4* p1 = (const float4*)(h + (size_t)row1 * H);
        __nv_bfloat16* zr0 = g_Zb + (size_t)row0 * ZK2;
        __nv_bfloat16* zr1 = g_Zb + (size_t)row1 * ZK2;
        #pragma unroll
        for (int j = 0; j < 8; j++) {
            h0p[j] = pack4bf(p0[j*32 + l]);
            h1p[j] = pack4bf(p1[j*32 + l]);
            *(uint2*)(zr0 + j*128 + 4*l) = h0p[j];
            *(uint2*)(zr1 + j*128 + 4*l) = h1p[j];
        }
    }

    // ---- phase A: scores via HFMA2 (partial bf16 accum, f32 reduce) ----
    float v0a = -1e30f, v0b = -1e30f, v1a = -1e30f, v1b = -1e30f;
    const __nv_bfloat162 z2 = __float2bfloat162_rn(0.f);
    for (int t = 0; t < T; t++) {
        const uint2* bt = bB + t*256;
        __nv_bfloat162 a0a = z2, a0b = z2, a1a = z2, a1b = z2;
        #pragma unroll
        for (int j = 0; j < 8; j++) {
            uint2 pk = bt[j*32 + l];
            __nv_bfloat162 b01 = *(__nv_bfloat162*)&pk.x;
            __nv_bfloat162 b23 = *(__nv_bfloat162*)&pk.y;
            a0a = __hfma2(b01, *(__nv_bfloat162*)&h0p[j].x, a0a);
            a0b = __hfma2(b23, *(__nv_bfloat162*)&h0p[j].y, a0b);
            a1a = __hfma2(b01, *(__nv_bfloat162*)&h1p[j].x, a1a);
            a1b = __hfma2(b23, *(__nv_bfloat162*)&h1p[j].y, a1b);
        }
        float2 f0 = __bfloat1622float2(a0a), f0q = __bfloat1622float2(a0b);
        float2 f1 = __bfloat1622float2(a1a), f1q = __bfloat1622float2(a1b);
        float s0 = (f0.x + f0.y) + (f0q.x + f0q.y);
        float s1 = (f1.x + f1.y) + (f1q.x + f1q.y);
        #pragma unroll
        for (int o = 16; o; o >>= 1) {
            s0 += __shfl_xor_sync(~0u, s0, o);
            s1 += __shfl_xor_sync(~0u, s1, o);
        }
        s0 *= 0.03125f; s1 *= 0.03125f;
        if (t < 32) { if (l == t)    { v0a = s0; v1a = s1; } }
        else        { if (l == t-32) { v0b = s0; v1b = s1; } }
    }

    // ---- softmax (per row, in-warp) ----
    float e0a, e0b, e1a, e1b;
    {
        float m0 = rmax32(fmaxf(v0a, (l < T-32) ? v0b : -1e30f));
        e0a = __expf(v0a - m0);
        e0b = (l < T-32) ? __expf(v0b - m0) : 0.f;
        float ss = e0a + e0b;
        #pragma unroll
        for (int o = 16; o; o >>= 1) ss += __shfl_xor_sync(~0u, ss, o);
        float inv = 1.f / ss; e0a *= inv; e0b *= inv;

        float m1 = rmax32(fmaxf(v1a, (l < T-32) ? v1b : -1e30f));
        e1a = __expf(v1a - m1);
        e1b = (l < T-32) ? __expf(v1b - m1) : 0.f;
        float s1s = e1a + e1b;
        #pragma unroll
        for (int o = 16; o; o >>= 1) s1s += __shfl_xor_sync(~0u, s1s, o);
        float inv1 = 1.f / s1s; e1a *= inv1; e1b *= inv1;
    }

    // attn columns [2048, 2112)
    {
        __nv_bfloat16* zr0 = g_Zb + (size_t)row0 * ZK2;
        __nv_bfloat16* zr1 = g_Zb + (size_t)row1 * ZK2;
        int i0 = 2*l, i1 = 2*l + 1;
        float r0lo0 = __shfl_sync(~0u, e0a, i0 & 31);
        float r0hi0 = __shfl_sync(~0u, e0b, (i0 >= 32) ? (i0 - 32) : 0);
        float r0lo1 = __shfl_sync(~0u, e0a, i1 & 31);
        float r0hi1 = __shfl_sync(~0u, e0b, (i1 >= 32) ? (i1 - 32) : 0);
        float r1lo0 = __shfl_sync(~0u, e1a, i0 & 31);
        float r1hi0 = __shfl_sync(~0u, e1b, (i0 >= 32) ? (i0 - 32) : 0);
        float r1lo1 = __shfl_sync(~0u, e1a, i1 & 31);
        float r1hi1 = __shfl_sync(~0u, e1b, (i1 >= 32) ? (i1 - 32) : 0);
        float a00 = (i0 < 32) ? r0lo0 : r0hi0; if (i0 >= T) a00 = 0.f;
        float a01 = (i1 < 32) ? r0lo1 : r0hi1; if (i1 >= T) a01 = 0.f;
        float a10 = (i0 < 32) ? r1lo0 : r1hi0; if (i0 >= T) a10 = 0.f;
        float a11 = (i1 < 32) ? r1lo1 : r1hi1; if (i1 >= T) a11 = 0.f;
        __nv_bfloat162 q0; q0.x = __float2bfloat16(a00); q0.y = __float2bfloat16(a01);
        __nv_bfloat162 q1; q1.x = __float2bfloat16(a10); q1.y = __float2bfloat16(a11);
        *(uint32_t*)(zr0 + 2048 + 2*l) = *(uint32_t*)&q0;
        *(uint32_t*)(zr1 + 2048 + 2*l) = *(uint32_t*)&q1;
    }

    // ---- phase B: aware accumulation in bf16x2 ----
    __nv_bfloat162 aw0[16], aw1[16];
    #pragma unroll
    for (int j = 0; j < 16; j++) { aw0[j] = z2; aw1[j] = z2; }
    for (int t = 0; t < T; t++) {
        float a0f = (t < 32) ? __shfl_sync(~0u, e0a, t) : __shfl_sync(~0u, e0b, t - 32);
        float a1f = (t < 32) ? __shfl_sync(~0u, e1a, t) : __shfl_sync(~0u, e1b, t - 32);
        __nv_bfloat162 a0v = __float2bfloat162_rn(a0f);
        __nv_bfloat162 a1v = __float2bfloat162_rn(a1f);
        const uint2* bt = bB + t*256;
        #pragma unroll
        for (int j = 0; j < 8; j++) {
            uint2 pk = bt[j*32 + l];
            __nv_bfloat162 b01 = *(__nv_bfloat162*)&pk.x;
            __nv_bfloat162 b23 = *(__nv_bfloat162*)&pk.y;
            aw0[2*j]   = __hfma2(b01, a0v, aw0[2*j]);
            aw0[2*j+1] = __hfma2(b23, a0v, aw0[2*j+1]);
            aw1[2*j]   = __hfma2(b01, a1v, aw1[2*j]);
            aw1[2*j+1] = __hfma2(b23, a1v, aw1[2*j+1]);
        }
    }

    // product h * aware (bf16x2 mul), store
    {
        __nv_bfloat16* zr0 = g_Zb + (size_t)row0 * ZK2;
        __nv_bfloat16* zr1 = g_Zb + (size_t)row1 * ZK2;
        #pragma unroll
        for (int j = 0; j < 8; j++) {
            __nv_bfloat162 p0x = __hmul2(aw0[2*j],   *(__nv_bfloat162*)&h0p[j].x);
            __nv_bfloat162 p0y = __hmul2(aw0[2*j+1], *(__nv_bfloat162*)&h0p[j].y);
            uint2 pk0; pk0.x = *(uint32_t*)&p0x; pk0.y = *(uint32_t*)&p0y;
            *(uint2*)(zr0 + 1024 + j*128 + 4*l) = pk0;
            __nv_bfloat162 p1x = __hmul2(aw1[2*j],   *(__nv_bfloat162*)&h1p[j].x);
            __nv_bfloat162 p1y = __hmul2(aw1[2*j+1], *(__nv_bfloat162*)&h1p[j].y);
            uint2 pk1; pk1.x = *(uint32_t*)&p1x; pk1.y = *(uint32_t*)&p1y;
            *(uint2*)(zr1 + 1024 + j*128 + 4*l) = pk1;
        }
    }
}

// ---------------------------------------------------------------------------
// k2: Yb = bf16(gelu(Z @ Wt^T + bc))  bf16 mma, BM=128 BN=128 BK=64,
// 3-stage cp.async, SW128 swizzle + ldmatrix, 8 warps (4x2), 2 CTAs/SM.
// ---------------------------------------------------------------------------
#define KBM 128
#define KBN 128
#define KBK 64
#define NKI (ZK2/KBK)            // 33
#define STG (KBM*128 + KBN*128)  // 32768 bytes
#define SMEM_K2 (3*STG)          // 98304

__device__ __forceinline__ void k2_load_stage(
    uint32_t sb, int tid, int j, const char* Zb, const char* Wb)
{
    uint32_t base = sb + (j % 3) * STG;
    int kb = j * 128;
    #pragma unroll
    for (int q = 0; q < 8; q++) {
        int idx = tid + 256*q;
        if (q < 4) {
            int m = idx >> 3, c = idx & 7;
            cp16(base + ((m*128 + c*16) ^ ((m & 7) << 4)),
                 Zb + (size_t)m * (ZK2*2) + kb + c*16);
        } else {
            int ci = idx - 1024;
            int n = ci >> 3, c = ci & 7;
            cp16(base + 16384 + ((n*128 + c*16) ^ ((n & 7) << 4)),
                 Wb + (size_t)n * (ZK2*2) + kb + c*16);
        }
    }
}

__global__ __launch_bounds__(256, 2) void k2_mma(const float* __restrict__ bc)
{
    extern __shared__ __align__(16) char smem[];
    uint32_t sb = smem_u32(smem);
    int tid = threadIdx.x, lane = tid & 31, wid = tid >> 5;
    int wm = wid & 3, wn = wid >> 2;
    int row0 = blockIdx.y * KBM, n0 = blockIdx.x * KBN;

    const char* Zb = (const char*)g_Zb + (size_t)row0 * (ZK2*2);
    const char* Wb = (const char*)g_Wt + (size_t)n0   * (ZK2*2);

    float acc[2][8][4];
    #pragma unroll
    for (int mt = 0; mt < 2; mt++)
        #pragma unroll
        for (int nt = 0; nt < 8; nt++)
            #pragma unroll
            for (int q = 0; q < 4; q++) acc[mt][nt][q] = 0.f;

    k2_load_stage(sb, tid, 0, Zb, Wb); CP_COMMIT();
    k2_load_stage(sb, tid, 1, Zb, Wb); CP_COMMIT();

    int r15 = lane & 15;
    int hb  = (lane >> 4) << 4;

    for (int i = 0; i < NKI; i++) {
        int j = i + 2;
        if (j < NKI) k2_load_stage(sb, tid, j, Zb, Wb);
        CP_COMMIT();
        CP_WAIT(2);
        __syncthreads();

        uint32_t Ab = sb + (i % 3) * STG;
        uint32_t Bb = Ab + 16384;
        #pragma unroll
        for (int kk = 0; kk < 4; kk++) {
            int kbyte = kk*32 + hb;
            uint32_t a[2][4];
            #pragma unroll
            for (int mt = 0; mt < 2; mt++) {
                int rr = wm*32 + mt*16 + r15;
                ldsm4(a[mt], Ab + rr*128 + (kbyte ^ ((rr & 7) << 4)));
            }
            #pragma unroll
            for (int ntp = 0; ntp < 4; ntp++) {
                int nr = wn*64 + ntp*16 + r15;
                uint32_t b[4];
                ldsm4(b, Bb + nr*128 + (kbyte ^ ((nr & 7) << 4)));
                #pragma unroll
                for (int mt = 0; mt < 2; mt++) {
                    mma_bf16(acc[mt][2*ntp],   a[mt], b[0], b[2]);
                    mma_bf16(acc[mt][2*ntp+1], a[mt], b[1], b[3]);
                }
            }
        }
        __syncthreads();
    }

    int g = lane >> 2, t4 = lane & 3;
    #pragma unroll
    for (int mt = 0; mt < 2; mt++) {
        #pragma unroll
        for (int nt = 0; nt < 8; nt++) {
            int r0 = row0 + wm*32 + mt*16 + g;
            int c  = n0 + wn*64 + nt*8 + 2*t4;
            float b0v = __ldg(bc + c), b1v = __ldg(bc + c + 1);
            __nv_bfloat162 o0, o1;
            o0.x = __float2bfloat16(gelu(acc[mt][nt][0] + b0v));
            o0.y = __float2bfloat16(gelu(acc[mt][nt][1] + b1v));
            o1.x = __float2bfloat16(gelu(acc[mt][nt][2] + b0v));
            o1.y = __float2bfloat16(gelu(acc[mt][nt][3] + b1v));
            *(uint32_t*)(g_Yb + (size_t)r0 * H + c) = *(uint32_t*)&o0;
            *(uint32_t*)(g_Yb + (size_t)(r0 + 8) * H + c) = *(uint32_t*)&o1;
        }
    }
}

// ---------------------------------------------------------------------------
// k3: logits = Yb @ W3^T + b_crf -> ner_scores (+ pads), via bf16 mma.
// BM=128, BN=64, BK=64, 3-stage. 8 warps as 4(m) x 2(n), warp tile 32x32.
// ---------------------------------------------------------------------------
#define STG3 (128*128 + 64*128)   // 24576 bytes
#define SMEM_K3 (3*STG3)          // 73728
#define NKI3 (H/64)               // 16

__device__ __forceinline__ void k3_load_stage(
    uint32_t sb, int tid, int j, const char* Yb)
{
    uint32_t base = sb + (j % 3) * STG3;
    int kb = j * 128;
    #pragma unroll
    for (int q = 0; q < 6; q++) {
        int idx = tid + 256*q;
        if (q < 4) {
            int m = idx >> 3, c = idx & 7;
            cp16(base + ((m*128 + c*16) ^ ((m & 7) << 4)),
                 Yb + (size_t)m * (H*2) + kb + c*16);
        } else {
            int ci = idx - 1024;
            int n = ci >> 3, c = ci & 7;
            cp16(base + 16384 + ((n*128 + c*16) ^ ((n & 7) << 4)),
                 (const char*)g_W3 + (size_t)n * (H*2) + kb + c*16);
        }
    }
}

__global__ __launch_bounds__(256, 2) void k3_mma(
    const float* __restrict__ bcrf, float* __restrict__ out)
{
    extern __shared__ __align__(16) char smem[];
    uint32_t sb = smem_u32(smem);
    int tid = threadIdx.x, lane = tid & 31, wid = tid >> 5;
    int wm = wid & 3, wn = wid >> 2;          // 4 x 2
    int row0 = blockIdx.x * 128;

    const char* Yb = (const char*)g_Yb + (size_t)row0 * (H*2);

    float acc[2][4][4];
    #pragma unroll
    for (int mt = 0; mt < 2; mt++)
        #pragma unroll
        for (int nt = 0; nt < 4; nt++)
            #pragma unroll
            for (int q = 0; q < 4; q++) acc[mt][nt][q] = 0.f;

    k3_load_stage(sb, tid, 0, Yb); CP_COMMIT();
    k3_load_stage(sb, tid, 1, Yb); CP_COMMIT();

    int r15 = lane & 15;
    int hb  = (lane >> 4) << 4;

    for (int i = 0; i < NKI3; i++) {
        int j = i + 2;
        if (j < NKI3) k3_load_stage(sb, tid, j, Yb);
        CP_COMMIT();
        CP_WAIT(2);
        __syncthreads();

        uint32_t Ab = sb + (i % 3) * STG3;
        uint32_t Bb = Ab + 16384;
        #pragma unroll
        for (int kk = 0; kk < 4; kk++) {
            int kbyte = kk*32 + hb;
            uint32_t a[2][4];
            #pragma unroll
            for (int mt = 0; mt < 2; mt++) {
                int rr = wm*32 + mt*16 + r15;
                ldsm4(a[mt], Ab + rr*128 + (kbyte ^ ((rr & 7) << 4)));
            }
            #pragma unroll
            for (int np = 0; np < 2; np++) {
                int nr = wn*32 + np*16 + r15;
                uint32_t b[4];
                ldsm4(b, Bb + nr*128 + (kbyte ^ ((nr & 7) << 4)));
                #pragma unroll
                for (int mt = 0; mt < 2; mt++) {
                    mma_bf16(acc[mt][2*np],   a[mt], b[0], b[2]);
                    mma_bf16(acc[mt][2*np+1], a[mt], b[1], b[3]);
                }
            }
        }
        __syncthreads();
    }

    int g = lane >> 2, t4 = lane & 3;
    #pragma unroll
    for (int mt = 0; mt < 2; mt++) {
        int r = row0 + wm*32 + mt*16 + g;
        #pragma unroll
        for (int nt = 0; nt < 4; nt++) {
            int c0 = wn*32 + nt*8 + 2*t4, c1 = c0 + 1;
            if (c0 < T) {
                float bv = __ldg(bcrf + c0);
                out[(size_t)r*LP + c0]     = acc[mt][nt][0] + bv;
                out[(size_t)(r+8)*LP + c0] = acc[mt][nt][2] + bv;
            }
            if (c1 < T) {
                float bv = __ldg(bcrf + c1);
                out[(size_t)r*LP + c1]     = acc[mt][nt][1] + bv;
                out[(size_t)(r+8)*LP + c1] = acc[mt][nt][3] + bv;
            }
        }
        if (wn == 1 && t4 == 0) {
            out[(size_t)r*LP + 37] = -10000.f;  out[(size_t)r*LP + 38] = -10000.f;
            out[(size_t)(r+8)*LP + 37] = -10000.f; out[(size_t)(r+8)*LP + 38] = -10000.f;
        }
    }
}

// ---------------------------------------------------------------------------
// k4: CRF loglik. One warp per batch; shuffle scan, redux-based max.
// ---------------------------------------------------------------------------
__global__ __launch_bounds__(32) void k4_crf(
    const float* __restrict__ scores, const int* __restrict__ labels,
    const int* __restrict__ lens, const float* __restrict__ trans,
    float* __restrict__ loss)
{
    extern __shared__ float sc[];   // S*LP floats
    int b = blockIdx.x;
    int lane = threadIdx.x;
    int len = lens[b];
    const int* lab = labels + b*S;

    {
        uint32_t sbase = smem_u32(sc);
        const float4* src = (const float4*)(scores + (size_t)b * S * LP);
        for (int i = lane; i < S*LP/4; i += 32)
            cp16(sbase + i*16, src + i);
        CP_COMMIT();
        CP_WAIT(0);
        __syncwarp();
    }

    float ET0[LP], ET1[LP], maxT0 = -1e30f, maxT1 = -1e30f;
    {
        const float* tr = trans + lane*LP;
        #pragma unroll
        for (int f = 0; f < LP; f++) maxT0 = fmaxf(maxT0, tr[f]);
        #pragma unroll
        for (int f = 0; f < LP; f++) ET0[f] = __expf(tr[f] - maxT0);
    }
    if (lane < LP-32) {
        const float* tr = trans + (32+lane)*LP;
        #pragma unroll
        for (int f = 0; f < LP; f++) maxT1 = fmaxf(maxT1, tr[f]);
        #pragma unroll
        for (int f = 0; f < LP; f++) ET1[f] = __expf(tr[f] - maxT1);
    }

    float g = 0.f;
    for (int s2 = lane; s2 < len; s2 += 32) g += sc[s2*LP + lab[s2]];
    for (int i = lane; i <= len; i += 32) {
        int frm = (i == 0)   ? T       : lab[i-1];
        int to  = (i == len) ? (T + 1) : lab[i];
        g += trans[to*LP + frm];
    }
    #pragma unroll
    for (int o = 16; o; o >>= 1) g += __shfl_xor_sync(~0u, g, o);

    float a0 = -100.f;
    float a1 = (lane == (T - 32)) ? 0.f : -100.f;

    for (int t = 0; t < len; t++) {
        float v = rmax32(fmaxf(a0, (lane < LP-32) ? a1 : -1e30f));
        float e0 = __expf(a0 - v);
        float e1 = (lane < LP-32) ? __expf(a1 - v) : 0.f;
        float s0a = 0.f, s0b = 0.f, s1a = 0.f, s1b = 0.f;
        #pragma unroll
        for (int f = 0; f < 32; f += 2) {
            float ea = __shfl_sync(~0u, e0, f);
            float eb = __shfl_sync(~0u, e0, f+1);
            s0a += ea*ET0[f];   s0b += eb*ET0[f+1];
            s1a += ea*ET1[f];   s1b += eb*ET1[f+1];
        }
        #pragma unroll
        for (int f = 0; f < LP-32; f++) {
            float ea = __shfl_sync(~0u, e1, f);
            s0a += ea*ET0[32+f];
            s1a += ea*ET1[32+f];
        }
        a0 = sc[t*LP + lane] + v + maxT0 + __logf(s0a + s0b);
        if (lane < LP-32)
            a1 = sc[t*LP + 32 + lane] + v + maxT1 + __logf(s1a + s1b);
    }

    a0 += trans[(T+1)*LP + lane];
    if (lane < LP-32) a1 += trans[(T+1)*LP + 32 + lane];
    float v = rmax32(fmaxf(a0, (lane < LP-32) ? a1 : -1e30f));
    float e = __expf(a0 - v) + ((lane < LP-32) ? __expf(a1 - v) : 0.f);
    #pragma unroll
    for (int o = 16; o; o >>= 1) e += __shfl_xor_sync(~0u, e, o);
    if (lane == 0) loss[b] = g - (v + logf(e));
}

// ---------------------------------------------------------------------------
extern "C" void kernel_launch(void* const* d_in, const int* in_sizes, int n_in,
                              void* d_out, int out_size)
{
    const float* h      = (const float*)d_in[0];
    const int*   lens   = (const int*)d_in[2];
    const int*   labels = (const int*)d_in[3];
    const float* bio    = (const float*)d_in[4];
    const float* W_cat  = (const float*)d_in[5];
    const float* b_cat  = (const float*)d_in[6];
    const float* W_crf  = (const float*)d_in[7];
    const float* b_crf  = (const float*)d_in[8];
    const float* trans  = (const float*)d_in[9];

    float* out = (float*)d_out;            // ner_scores [B,S,LP] then loss [B]
    float* loss = out + (size_t)B * S * LP;

    size_t smem1  = (size_t)(T*H) * sizeof(__nv_bfloat16);  // 75776
    size_t smemW2 = (size_t)(T*H) * sizeof(float);          // 151552
    size_t smem4  = (size_t)(S*LP) * sizeof(float);         // 79872

    static int attr_done = 0;
    if (!attr_done) {
        cudaFuncSetAttribute(k1_bio_attn, cudaFuncAttributeMaxDynamicSharedMemorySize, (int)smem1);
        cudaFuncSetAttribute(k_bw2,       cudaFuncAttributeMaxDynamicSharedMemorySize, (int)smemW2);
        cudaFuncSetAttribute(k2_mma,      cudaFuncAttributeMaxDynamicSharedMemorySize, SMEM_K2);
        cudaFuncSetAttribute(k3_mma,      cudaFuncAttributeMaxDynamicSharedMemorySize, SMEM_K3);
        cudaFuncSetAttribute(k4_crf,      cudaFuncAttributeMaxDynamicSharedMemorySize, (int)smem4);
        attr_done = 1;
    }

    k0_transpose<<<dim3(2048/32, H/32), dim3(32, 8)>>>(W_cat);
    kzero<<<(H*27 + 255)/256, 256>>>();
    kw3<<<dim3(H/32, 2), dim3(32, 8)>>>(W_crf);
    k_bw2<<<32, 256, smemW2>>>(bio, W_cat);
    k1_bio_attn<<<BS/16, 256, smem1>>>(h, bio);
    k2_mma<<<dim3(H/KBN, BS/KBM), 256, SMEM_K2>>>(b_cat);
    k3_mma<<<BS/128, 256, SMEM_K3>>>(b_crf, out);
    k4_crf<<<B, 32, smem4>>>(out, labels, lens, trans, loss);
}

// round 8
// speedup vs baseline: 1.8106x; 1.2907x over previous
#include <cuda_runtime.h>
#include <cuda_bf16.h>
#include <cstdint>
#include <math.h>

// Problem constants
#define B   32
#define S   512
#define H   1024
#define T   37
#define LP  39
#define BS  (B*S)          // 16384
#define ZK2 2112           // 1024 (h) + 1024 (h*aware) + 64 (attn pad)
#define KSPLIT 8

// Scratch (device-global)
__device__ __align__(256) __nv_bfloat16 g_Zb[BS * ZK2];  // 66 MiB
__device__ __align__(256) __nv_bfloat16 g_Wt[H * ZK2];   // [n][k]  4.3 MiB
__device__ __align__(256) __nv_bfloat16 g_Yb[BS * H];    // gelu out, bf16, 32 MiB
__device__ __align__(256) __nv_bfloat16 g_W3[64 * H];    // W_crf^T padded, bf16
__device__ __align__(256) float g_BW2p[KSPLIT * T * H];  // bw2 partials, 1.2 MiB

// ===========================================================================
// helpers
// ===========================================================================
__device__ __forceinline__ uint32_t smem_u32(const void* p) {
    uint32_t a;
    asm("{ .reg .u64 t; cvta.to.shared.u64 t, %1; cvt.u32.u64 %0, t; }"
        : "=r"(a) : "l"(p));
    return a;
}
__device__ __forceinline__ void cp16(uint32_t dst, const void* src) {
    asm volatile("cp.async.cg.shared.global [%0], [%1], 16;\n" :: "r"(dst), "l"(src));
}
#define CP_COMMIT() asm volatile("cp.async.commit_group;\n" ::: "memory")
#define CP_WAIT(n)  asm volatile("cp.async.wait_group %0;\n" :: "n"(n) : "memory")

__device__ __forceinline__ float gelu(float v) {
    return 0.5f * v * (1.f + erff(v * 0.70710678118654752f));
}
__device__ __forceinline__ void ldsm4(uint32_t* r, uint32_t addr) {
    asm volatile("ldmatrix.sync.aligned.m8n8.x4.shared.b16 {%0,%1,%2,%3}, [%4];"
        : "=r"(r[0]), "=r"(r[1]), "=r"(r[2]), "=r"(r[3]) : "r"(addr));
}
__device__ __forceinline__ void mma_bf16(
    float* d, const uint32_t* a, uint32_t b0, uint32_t b1)
{
    asm volatile(
        "mma.sync.aligned.m16n8k16.row.col.f32.bf16.bf16.f32 "
        "{%0,%1,%2,%3}, {%4,%5,%6,%7}, {%8,%9}, {%0,%1,%2,%3};"
        : "+f"(d[0]), "+f"(d[1]), "+f"(d[2]), "+f"(d[3])
        : "r"(a[0]), "r"(a[1]), "r"(a[2]), "r"(a[3]), "r"(b0), "r"(b1));
}
__device__ __forceinline__ float rmax32(float x) {
    uint32_t k = __float_as_uint(x);
    k = (k & 0x80000000u) ? ~k : (k | 0x80000000u);
    k = __reduce_max_sync(0xFFFFFFFFu, k);
    return __uint_as_float((k & 0x80000000u) ? (k & 0x7FFFFFFFu) : ~k);
}
__device__ __forceinline__ uint2 pack4bf(float4 v) {
    __nv_bfloat162 p0; p0.x = __float2bfloat16(v.x); p0.y = __float2bfloat16(v.y);
    __nv_bfloat162 p1; p1.x = __float2bfloat16(v.z); p1.y = __float2bfloat16(v.w);
    uint2 r; r.x = *(uint32_t*)&p0; r.y = *(uint32_t*)&p1; return r;
}

// ---------------------------------------------------------------------------
// k0: g_Wt[n][k] = bf16(W_cat[src(k)][n]) for k<2048 (src skips W2 block)
// ---------------------------------------------------------------------------
__global__ __launch_bounds__(256) void k0_transpose(const float* __restrict__ W)
{
    __shared__ float tile[32][33];
    int k0 = blockIdx.x * 32, n0 = blockIdx.y * 32;
    int tx = threadIdx.x, ty = threadIdx.y;
    #pragma unroll
    for (int j = 0; j < 32; j += 8) {
        int k = k0 + ty + j;
        int src = (k < H) ? k : (k + H);
        tile[ty + j][tx] = W[(size_t)src * H + n0 + tx];
    }
    __syncthreads();
    #pragma unroll
    for (int j = 0; j < 32; j += 8) {
        int n = n0 + ty + j;
        g_Wt[(size_t)n * ZK2 + k0 + tx] = __float2bfloat16(tile[tx][ty + j]);
    }
}

// ---------------------------------------------------------------------------
// kw3: transpose W_crf [H][T] f32 -> g_W3 [64][H] bf16 (rows T..63 zero)
// ---------------------------------------------------------------------------
__global__ __launch_bounds__(256) void kw3(const float* __restrict__ Wc)
{
    __shared__ float tile[32][33];
    int k0 = blockIdx.x * 32, t0 = blockIdx.y * 32;
    int tx = threadIdx.x, ty = threadIdx.y;
    #pragma unroll
    for (int j = 0; j < 32; j += 8) {
        int k = k0 + ty + j, t = t0 + tx;
        tile[ty + j][tx] = (t < T) ? Wc[(size_t)k * T + t] : 0.f;
    }
    __syncthreads();
    #pragma unroll
    for (int j = 0; j < 32; j += 8) {
        int t = t0 + ty + j;
        g_W3[(size_t)t * H + k0 + tx] = __float2bfloat16(tile[tx][ty + j]);
    }
}

// ---------------------------------------------------------------------------
// k_bw2: partial[by][t][n] = sum_{k in chunk} bio[t][k] * W_cat[1024+k][n]
// grid (H/32, KSPLIT): 256 blocks, 128 k-iters each.
// ---------------------------------------------------------------------------
__global__ __launch_bounds__(256) void k_bw2(
    const float* __restrict__ bio, const float* __restrict__ W)
{
    __shared__ float bioS[T * 128 + 32];    // [T][128] k-chunk of bio
    int tid = threadIdx.x;
    int k0 = blockIdx.y * 128;
    for (int i = tid; i < T * 32; i += 256) {           // 37 rows x 32 f4
        int t = i >> 5, c = i & 31;
        ((float4*)&bioS[t*128])[c] = ((const float4*)(bio + (size_t)t * H + k0))[c];
    }
    __syncthreads();

    int n = blockIdx.x * 32 + (tid & 31);
    int th = tid >> 5;
    float acc[5] = {0.f, 0.f, 0.f, 0.f, 0.f};
    #pragma unroll 4
    for (int k = 0; k < 128; k++) {
        float w = W[(size_t)(H + k0 + k) * H + n];
        #pragma unroll
        for (int j = 0; j < 5; j++) {
            int t = th + 8*j;
            float bv = (t < T) ? bioS[t*128 + k] : 0.f;
            acc[j] += bv * w;
        }
    }
    float* pp = g_BW2p + (size_t)blockIdx.y * T * H;
    #pragma unroll
    for (int j = 0; j < 5; j++) {
        int t = th + 8*j;
        if (t < T) pp[t*H + n] = acc[j];
    }
}

// ---------------------------------------------------------------------------
// k_bw2fin: g_Wt[n][2048+c] = bf16(sum_s partial[s][c][n]) for c<T else 0.
// Also covers the pad columns (absorbs old kzero).
// ---------------------------------------------------------------------------
__global__ __launch_bounds__(256) void k_bw2fin()
{
    int idx = blockIdx.x * 256 + threadIdx.x;     // 0 .. H*64-1
    int n = idx >> 6, c = idx & 63;
    float s = 0.f;
    if (c < T) {
        #pragma unroll
        for (int q = 0; q < KSPLIT; q++)
            s += g_BW2p[(size_t)q * T * H + c*H + n];
    }
    g_Wt[(size_t)n * ZK2 + 2048 + c] = __float2bfloat16(s);
}

// ---------------------------------------------------------------------------
// k1: 2 rows per warp, bf16 bio tile in smem, HFMA2 bf16x2 arithmetic.
// scores -> softmax -> aware; Z = bf16[h | h*aware | attn]
// ---------------------------------------------------------------------------
__global__ __launch_bounds__(256, 2) void k1_bio_attn(
    const float* __restrict__ h, const float* __restrict__ bio)
{
    extern __shared__ __align__(16) __nv_bfloat16 bioB[];   // [T][H] bf16
    int tid = threadIdx.x;
    for (int i = tid; i < T*H/2; i += 256) {
        float2 v = ((const float2*)bio)[i];
        __nv_bfloat162 p; p.x = __float2bfloat16(v.x); p.y = __float2bfloat16(v.y);
        ((__nv_bfloat162*)bioB)[i] = p;
    }
    __syncthreads();

    int wid = tid >> 5, l = tid & 31;
    int row0 = (blockIdx.x * 8 + wid) * 2;
    int row1 = row0 + 1;
    const uint2* bB = (const uint2*)bioB;   // 4 bf16 per entry, row stride 256

    // h rows as packed bf16 (also the Z h-part payload)
    uint2 h0p[8], h1p[8];
    {
        const float4* p0 = (const float4*)(h + (size_t)row0 * H);
        const float4* p1 = (const float4*)(h + (size_t)row1 * H);
        __nv_bfloat16* zr0 = g_Zb + (size_t)row0 * ZK2;
        __nv_bfloat16* zr1 = g_Zb + (size_t)row1 * ZK2;
        #pragma unroll
        for (int j = 0; j < 8; j++) {
            h0p[j] = pack4bf(p0[j*32 + l]);
            h1p[j] = pack4bf(p1[j*32 + l]);
            *(uint2*)(zr0 + j*128 + 4*l) = h0p[j];
            *(uint2*)(zr1 + j*128 + 4*l) = h1p[j];
        }
    }

    // ---- phase A: scores via HFMA2 (partial bf16 accum, f32 reduce) ----
    float v0a = -1e30f, v0b = -1e30f, v1a = -1e30f, v1b = -1e30f;
    const __nv_bfloat162 z2 = __float2bfloat162_rn(0.f);
    for (int t = 0; t < T; t++) {
        const uint2* bt = bB + t*256;
        __nv_bfloat162 a0a = z2, a0b = z2, a1a = z2, a1b = z2;
        #pragma unroll
        for (int j = 0; j < 8; j++) {
            uint2 pk = bt[j*32 + l];
            __nv_bfloat162 b01 = *(__nv_bfloat162*)&pk.x;
            __nv_bfloat162 b23 = *(__nv_bfloat162*)&pk.y;
            a0a = __hfma2(b01, *(__nv_bfloat162*)&h0p[j].x, a0a);
            a0b = __hfma2(b23, *(__nv_bfloat162*)&h0p[j].y, a0b);
            a1a = __hfma2(b01, *(__nv_bfloat162*)&h1p[j].x, a1a);
            a1b = __hfma2(b23, *(__nv_bfloat162*)&h1p[j].y, a1b);
        }
        float2 f0 = __bfloat1622float2(a0a), f0q = __bfloat1622float2(a0b);
        float2 f1 = __bfloat1622float2(a1a), f1q = __bfloat1622float2(a1b);
        float s0 = (f0.x + f0.y) + (f0q.x + f0q.y);
        float s1 = (f1.x + f1.y) + (f1q.x + f1q.y);
        #pragma unroll
        for (int o = 16; o; o >>= 1) {
            s0 += __shfl_xor_sync(~0u, s0, o);
            s1 += __shfl_xor_sync(~0u, s1, o);
        }
        s0 *= 0.03125f; s1 *= 0.03125f;
        if (t < 32) { if (l == t)    { v0a = s0; v1a = s1; } }
        else        { if (l == t-32) { v0b = s0; v1b = s1; } }
    }

    // ---- softmax (per row, in-warp) ----
    float e0a, e0b, e1a, e1b;
    {
        float m0 = rmax32(fmaxf(v0a, (l < T-32) ? v0b : -1e30f));
        e0a = __expf(v0a - m0);
        e0b = (l < T-32) ? __expf(v0b - m0) : 0.f;
        float ss = e0a + e0b;
        #pragma unroll
        for (int o = 16; o; o >>= 1) ss += __shfl_xor_sync(~0u, ss, o);
        float inv = 1.f / ss; e0a *= inv; e0b *= inv;

        float m1 = rmax32(fmaxf(v1a, (l < T-32) ? v1b : -1e30f));
        e1a = __expf(v1a - m1);
        e1b = (l < T-32) ? __expf(v1b - m1) : 0.f;
        float s1s = e1a + e1b;
        #pragma unroll
        for (int o = 16; o; o >>= 1) s1s += __shfl_xor_sync(~0u, s1s, o);
        float inv1 = 1.f / s1s; e1a *= inv1; e1b *= inv1;
    }

    // attn columns [2048, 2112)
    {
        __nv_bfloat16* zr0 = g_Zb + (size_t)row0 * ZK2;
        __nv_bfloat16* zr1 = g_Zb + (size_t)row1 * ZK2;
        int i0 = 2*l, i1 = 2*l + 1;
        float r0lo0 = __shfl_sync(~0u, e0a, i0 & 31);
        float r0hi0 = __shfl_sync(~0u, e0b, (i0 >= 32) ? (i0 - 32) : 0);
        float r0lo1 = __shfl_sync(~0u, e0a, i1 & 31);
        float r0hi1 = __shfl_sync(~0u, e0b, (i1 >= 32) ? (i1 - 32) : 0);
        float r1lo0 = __shfl_sync(~0u, e1a, i0 & 31);
        float r1hi0 = __shfl_sync(~0u, e1b, (i0 >= 32) ? (i0 - 32) : 0);
        float r1lo1 = __shfl_sync(~0u, e1a, i1 & 31);
        float r1hi1 = __shfl_sync(~0u, e1b, (i1 >= 32) ? (i1 - 32) : 0);
        float a00 = (i0 < 32) ? r0lo0 : r0hi0; if (i0 >= T) a00 = 0.f;
        float a01 = (i1 < 32) ? r0lo1 : r0hi1; if (i1 >= T) a01 = 0.f;
        float a10 = (i0 < 32) ? r1lo0 : r1hi0; if (i0 >= T) a10 = 0.f;
        float a11 = (i1 < 32) ? r1lo1 : r1hi1; if (i1 >= T) a11 = 0.f;
        __nv_bfloat162 q0; q0.x = __float2bfloat16(a00); q0.y = __float2bfloat16(a01);
        __nv_bfloat162 q1; q1.x = __float2bfloat16(a10); q1.y = __float2bfloat16(a11);
        *(uint32_t*)(zr0 + 2048 + 2*l) = *(uint32_t*)&q0;
        *(uint32_t*)(zr1 + 2048 + 2*l) = *(uint32_t*)&q1;
    }

    // ---- phase B: aware accumulation in bf16x2 ----
    __nv_bfloat162 aw0[16], aw1[16];
    #pragma unroll
    for (int j = 0; j < 16; j++) { aw0[j] = z2; aw1[j] = z2; }
    for (int t = 0; t < T; t++) {
        float a0f = (t < 32) ? __shfl_sync(~0u, e0a, t) : __shfl_sync(~0u, e0b, t - 32);
        float a1f = (t < 32) ? __shfl_sync(~0u, e1a, t) : __shfl_sync(~0u, e1b, t - 32);
        __nv_bfloat162 a0v = __float2bfloat162_rn(a0f);
        __nv_bfloat162 a1v = __float2bfloat162_rn(a1f);
        const uint2* bt = bB + t*256;
        #pragma unroll
        for (int j = 0; j < 8; j++) {
            uint2 pk = bt[j*32 + l];
            __nv_bfloat162 b01 = *(__nv_bfloat162*)&pk.x;
            __nv_bfloat162 b23 = *(__nv_bfloat162*)&pk.y;
            aw0[2*j]   = __hfma2(b01, a0v, aw0[2*j]);
            aw0[2*j+1] = __hfma2(b23, a0v, aw0[2*j+1]);
            aw1[2*j]   = __hfma2(b01, a1v, aw1[2*j]);
            aw1[2*j+1] = __hfma2(b23, a1v, aw1[2*j+1]);
        }
    }

    // product h * aware (bf16x2 mul), store
    {
        __nv_bfloat16* zr0 = g_Zb + (size_t)row0 * ZK2;
        __nv_bfloat16* zr1 = g_Zb + (size_t)row1 * ZK2;
        #pragma unroll
        for (int j = 0; j < 8; j++) {
            __nv_bfloat162 p0x = __hmul2(aw0[2*j],   *(__nv_bfloat162*)&h0p[j].x);
            __nv_bfloat162 p0y = __hmul2(aw0[2*j+1], *(__nv_bfloat162*)&h0p[j].y);
            uint2 pk0; pk0.x = *(uint32_t*)&p0x; pk0.y = *(uint32_t*)&p0y;
            *(uint2*)(zr0 + 1024 + j*128 + 4*l) = pk0;
            __nv_bfloat162 p1x = __hmul2(aw1[2*j],   *(__nv_bfloat162*)&h1p[j].x);
            __nv_bfloat162 p1y = __hmul2(aw1[2*j+1], *(__nv_bfloat162*)&h1p[j].y);
            uint2 pk1; pk1.x = *(uint32_t*)&p1x; pk1.y = *(uint32_t*)&p1y;
            *(uint2*)(zr1 + 1024 + j*128 + 4*l) = pk1;
        }
    }
}

// ---------------------------------------------------------------------------
// k2: Yb = bf16(gelu(Z @ Wt^T + bc))  bf16 mma, BM=128 BN=128 BK=64,
// 3-stage cp.async, SW128 swizzle + ldmatrix, 8 warps (4x2), 2 CTAs/SM.
// ---------------------------------------------------------------------------
#define KBM 128
#define KBN 128
#define KBK 64
#define NKI (ZK2/KBK)            // 33
#define STG (KBM*128 + KBN*128)  // 32768 bytes
#define SMEM_K2 (3*STG)          // 98304

__device__ __forceinline__ void k2_load_stage(
    uint32_t sb, int tid, int j, const char* Zb, const char* Wb)
{
    uint32_t base = sb + (j % 3) * STG;
    int kb = j * 128;
    #pragma unroll
    for (int q = 0; q < 8; q++) {
        int idx = tid + 256*q;
        if (q < 4) {
            int m = idx >> 3, c = idx & 7;
            cp16(base + ((m*128 + c*16) ^ ((m & 7) << 4)),
                 Zb + (size_t)m * (ZK2*2) + kb + c*16);
        } else {
            int ci = idx - 1024;
            int n = ci >> 3, c = ci & 7;
            cp16(base + 16384 + ((n*128 + c*16) ^ ((n & 7) << 4)),
                 Wb + (size_t)n * (ZK2*2) + kb + c*16);
        }
    }
}

__global__ __launch_bounds__(256, 2) void k2_mma(const float* __restrict__ bc)
{
    extern __shared__ __align__(16) char smem[];
    uint32_t sb = smem_u32(smem);
    int tid = threadIdx.x, lane = tid & 31, wid = tid >> 5;
    int wm = wid & 3, wn = wid >> 2;
    int row0 = blockIdx.y * KBM, n0 = blockIdx.x * KBN;

    const char* Zb = (const char*)g_Zb + (size_t)row0 * (ZK2*2);
    const char* Wb = (const char*)g_Wt + (size_t)n0   * (ZK2*2);

    float acc[2][8][4];
    #pragma unroll
    for (int mt = 0; mt < 2; mt++)
        #pragma unroll
        for (int nt = 0; nt < 8; nt++)
            #pragma unroll
            for (int q = 0; q < 4; q++) acc[mt][nt][q] = 0.f;

    k2_load_stage(sb, tid, 0, Zb, Wb); CP_COMMIT();
    k2_load_stage(sb, tid, 1, Zb, Wb); CP_COMMIT();

    int r15 = lane & 15;
    int hb  = (lane >> 4) << 4;

    for (int i = 0; i < NKI; i++) {
        int j = i + 2;
        if (j < NKI) k2_load_stage(sb, tid, j, Zb, Wb);
        CP_COMMIT();
        CP_WAIT(2);
        __syncthreads();

        uint32_t Ab = sb + (i % 3) * STG;
        uint32_t Bb = Ab + 16384;
        #pragma unroll
        for (int kk = 0; kk < 4; kk++) {
            int kbyte = kk*32 + hb;
            uint32_t a[2][4];
            #pragma unroll
            for (int mt = 0; mt < 2; mt++) {
                int rr = wm*32 + mt*16 + r15;
                ldsm4(a[mt], Ab + rr*128 + (kbyte ^ ((rr & 7) << 4)));
            }
            #pragma unroll
            for (int ntp = 0; ntp < 4; ntp++) {
                int nr = wn*64 + ntp*16 + r15;
                uint32_t b[4];
                ldsm4(b, Bb + nr*128 + (kbyte ^ ((nr & 7) << 4)));
                #pragma unroll
                for (int mt = 0; mt < 2; mt++) {
                    mma_bf16(acc[mt][2*ntp],   a[mt], b[0], b[2]);
                    mma_bf16(acc[mt][2*ntp+1], a[mt], b[1], b[3]);
                }
            }
        }
        __syncthreads();
    }

    int g = lane >> 2, t4 = lane & 3;
    #pragma unroll
    for (int mt = 0; mt < 2; mt++) {
        #pragma unroll
        for (int nt = 0; nt < 8; nt++) {
            int r0 = row0 + wm*32 + mt*16 + g;
            int c  = n0 + wn*64 + nt*8 + 2*t4;
            float b0v = __ldg(bc + c), b1v = __ldg(bc + c + 1);
            __nv_bfloat162 o0, o1;
            o0.x = __float2bfloat16(gelu(acc[mt][nt][0] + b0v));
            o0.y = __float2bfloat16(gelu(acc[mt][nt][1] + b1v));
            o1.x = __float2bfloat16(gelu(acc[mt][nt][2] + b0v));
            o1.y = __float2bfloat16(gelu(acc[mt][nt][3] + b1v));
            *(uint32_t*)(g_Yb + (size_t)r0 * H + c) = *(uint32_t*)&o0;
            *(uint32_t*)(g_Yb + (size_t)(r0 + 8) * H + c) = *(uint32_t*)&o1;
        }
    }
}

// ---------------------------------------------------------------------------
// k3: logits = Yb @ W3^T + b_crf -> ner_scores (+ pads), via bf16 mma.
// BM=128, BN=64, BK=64, 3-stage. 8 warps as 4(m) x 2(n), warp tile 32x32.
// ---------------------------------------------------------------------------
#define STG3 (128*128 + 64*128)   // 24576 bytes
#define SMEM_K3 (3*STG3)          // 73728
#define NKI3 (H/64)               // 16

__device__ __forceinline__ void k3_load_stage(
    uint32_t sb, int tid, int j, const char* Yb)
{
    uint32_t base = sb + (j % 3) * STG3;
    int kb = j * 128;
    #pragma unroll
    for (int q = 0; q < 6; q++) {
        int idx = tid + 256*q;
        if (q < 4) {
            int m = idx >> 3, c = idx & 7;
            cp16(base + ((m*128 + c*16) ^ ((m & 7) << 4)),
                 Yb + (size_t)m * (H*2) + kb + c*16);
        } else {
            int ci = idx - 1024;
            int n = ci >> 3, c = ci & 7;
            cp16(base + 16384 + ((n*128 + c*16) ^ ((n & 7) << 4)),
                 (const char*)g_W3 + (size_t)n * (H*2) + kb + c*16);
        }
    }
}

__global__ __launch_bounds__(256, 2) void k3_mma(
    const float* __restrict__ bcrf, float* __restrict__ out)
{
    extern __shared__ __align__(16) char smem[];
    uint32_t sb = smem_u32(smem);
    int tid = threadIdx.x, lane = tid & 31, wid = tid >> 5;
    int wm = wid & 3, wn = wid >> 2;          // 4 x 2
    int row0 = blockIdx.x * 128;

    const char* Yb = (const char*)g_Yb + (size_t)row0 * (H*2);

    float acc[2][4][4];
    #pragma unroll
    for (int mt = 0; mt < 2; mt++)
        #pragma unroll
        for (int nt = 0; nt < 4; nt++)
            #pragma unroll
            for (int q = 0; q < 4; q++) acc[mt][nt][q] = 0.f;

    k3_load_stage(sb, tid, 0, Yb); CP_COMMIT();
    k3_load_stage(sb, tid, 1, Yb); CP_COMMIT();

    int r15 = lane & 15;
    int hb  = (lane >> 4) << 4;

    for (int i = 0; i < NKI3; i++) {
        int j = i + 2;
        if (j < NKI3) k3_load_stage(sb, tid, j, Yb);
        CP_COMMIT();
        CP_WAIT(2);
        __syncthreads();

        uint32_t Ab = sb + (i % 3) * STG3;
        uint32_t Bb = Ab + 16384;
        #pragma unroll
        for (int kk = 0; kk < 4; kk++) {
            int kbyte = kk*32 + hb;
            uint32_t a[2][4];
            #pragma unroll
            for (int mt = 0; mt < 2; mt++) {
                int rr = wm*32 + mt*16 + r15;
                ldsm4(a[mt], Ab + rr*128 + (kbyte ^ ((rr & 7) << 4)));
            }
            #pragma unroll
            for (int np = 0; np < 2; np++) {
                int nr = wn*32 + np*16 + r15;
                uint32_t b[4];
                ldsm4(b, Bb + nr*128 + (kbyte ^ ((nr & 7) << 4)));
                #pragma unroll
                for (int mt = 0; mt < 2; mt++) {
                    mma_bf16(acc[mt][2*np],   a[mt], b[0], b[2]);
                    mma_bf16(acc[mt][2*np+1], a[mt], b[1], b[3]);
                }
            }
        }
        __syncthreads();
    }

    int g = lane >> 2, t4 = lane & 3;
    #pragma unroll
    for (int mt = 0; mt < 2; mt++) {
        int r = row0 + wm*32 + mt*16 + g;
        #pragma unroll
        for (int nt = 0; nt < 4; nt++) {
            int c0 = wn*32 + nt*8 + 2*t4, c1 = c0 + 1;
            if (c0 < T) {
                float bv = __ldg(bcrf + c0);
                out[(size_t)r*LP + c0]     = acc[mt][nt][0] + bv;
                out[(size_t)(r+8)*LP + c0] = acc[mt][nt][2] + bv;
            }
            if (c1 < T) {
                float bv = __ldg(bcrf + c1);
                out[(size_t)r*LP + c1]     = acc[mt][nt][1] + bv;
                out[(size_t)(r+8)*LP + c1] = acc[mt][nt][3] + bv;
            }
        }
        if (wn == 1 && t4 == 0) {
            out[(size_t)r*LP + 37] = -10000.f;  out[(size_t)r*LP + 38] = -10000.f;
            out[(size_t)(r+8)*LP + 37] = -10000.f; out[(size_t)(r+8)*LP + 38] = -10000.f;
        }
    }
}

// ---------------------------------------------------------------------------
// k4: CRF loglik. One warp per batch; shuffle scan, redux-based max.
// ---------------------------------------------------------------------------
__global__ __launch_bounds__(32) void k4_crf(
    const float* __restrict__ scores, const int* __restrict__ labels,
    const int* __restrict__ lens, const float* __restrict__ trans,
    float* __restrict__ loss)
{
    extern __shared__ float sc[];   // S*LP floats
    int b = blockIdx.x;
    int lane = threadIdx.x;
    int len = lens[b];
    const int* lab = labels + b*S;

    {
        uint32_t sbase = smem_u32(sc);
        const float4* src = (const float4*)(scores + (size_t)b * S * LP);
        for (int i = lane; i < S*LP/4; i += 32)
            cp16(sbase + i*16, src + i);
        CP_COMMIT();
        CP_WAIT(0);
        __syncwarp();
    }

    float ET0[LP], ET1[LP], maxT0 = -1e30f, maxT1 = -1e30f;
    {
        const float* tr = trans + lane*LP;
        #pragma unroll
        for (int f = 0; f < LP; f++) maxT0 = fmaxf(maxT0, tr[f]);
        #pragma unroll
        for (int f = 0; f < LP; f++) ET0[f] = __expf(tr[f] - maxT0);
    }
    if (lane < LP-32) {
        const float* tr = trans + (32+lane)*LP;
        #pragma unroll
        for (int f = 0; f < LP; f++) maxT1 = fmaxf(maxT1, tr[f]);
        #pragma unroll
        for (int f = 0; f < LP; f++) ET1[f] = __expf(tr[f] - maxT1);
    }

    float g = 0.f;
    for (int s2 = lane; s2 < len; s2 += 32) g += sc[s2*LP + lab[s2]];
    for (int i = lane; i <= len; i += 32) {
        int frm = (i == 0)   ? T       : lab[i-1];
        int to  = (i == len) ? (T + 1) : lab[i];
        g += trans[to*LP + frm];
    }
    #pragma unroll
    for (int o = 16; o; o >>= 1) g += __shfl_xor_sync(~0u, g, o);

    float a0 = -100.f;
    float a1 = (lane == (T - 32)) ? 0.f : -100.f;

    for (int t = 0; t < len; t++) {
        float v = rmax32(fmaxf(a0, (lane < LP-32) ? a1 : -1e30f));
        float e0 = __expf(a0 - v);
        float e1 = (lane < LP-32) ? __expf(a1 - v) : 0.f;
        float s0a = 0.f, s0b = 0.f, s1a = 0.f, s1b = 0.f;
        #pragma unroll
        for (int f = 0; f < 32; f += 2) {
            float ea = __shfl_sync(~0u, e0, f);
            float eb = __shfl_sync(~0u, e0, f+1);
            s0a += ea*ET0[f];   s0b += eb*ET0[f+1];
            s1a += ea*ET1[f];   s1b += eb*ET1[f+1];
        }
        #pragma unroll
        for (int f = 0; f < LP-32; f++) {
            float ea = __shfl_sync(~0u, e1, f);
            s0a += ea*ET0[32+f];
            s1a += ea*ET1[32+f];
        }
        a0 = sc[t*LP + lane] + v + maxT0 + __logf(s0a + s0b);
        if (lane < LP-32)
            a1 = sc[t*LP + 32 + lane] + v + maxT1 + __logf(s1a + s1b);
    }

    a0 += trans[(T+1)*LP + lane];
    if (lane < LP-32) a1 += trans[(T+1)*LP + 32 + lane];
    float v = rmax32(fmaxf(a0, (lane < LP-32) ? a1 : -1e30f));
    float e = __expf(a0 - v) + ((lane < LP-32) ? __expf(a1 - v) : 0.f);
    #pragma unroll
    for (int o = 16; o; o >>= 1) e += __shfl_xor_sync(~0u, e, o);
    if (lane == 0) loss[b] = g - (v + logf(e));
}

// ---------------------------------------------------------------------------
extern "C" void kernel_launch(void* const* d_in, const int* in_sizes, int n_in,
                              void* d_out, int out_size)
{
    const float* h      = (const float*)d_in[0];
    const int*   lens   = (const int*)d_in[2];
    const int*   labels = (const int*)d_in[3];
    const float* bio    = (const float*)d_in[4];
    const float* W_cat  = (const float*)d_in[5];
    const float* b_cat  = (const float*)d_in[6];
    const float* W_crf  = (const float*)d_in[7];
    const float* b_crf  = (const float*)d_in[8];
    const float* trans  = (const float*)d_in[9];

    float* out = (float*)d_out;            // ner_scores [B,S,LP] then loss [B]
    float* loss = out + (size_t)B * S * LP;

    size_t smem1  = (size_t)(T*H) * sizeof(__nv_bfloat16);  // 75776
    size_t smem4  = (size_t)(S*LP) * sizeof(float);         // 79872

    static int attr_done = 0;
    if (!attr_done) {
        cudaFuncSetAttribute(k1_bio_attn, cudaFuncAttributeMaxDynamicSharedMemorySize, (int)smem1);
        cudaFuncSetAttribute(k2_mma,      cudaFuncAttributeMaxDynamicSharedMemorySize, SMEM_K2);
        cudaFuncSetAttribute(k3_mma,      cudaFuncAttributeMaxDynamicSharedMemorySize, SMEM_K3);
        cudaFuncSetAttribute(k4_crf,      cudaFuncAttributeMaxDynamicSharedMemorySize, (int)smem4);
        attr_done = 1;
    }

    k_bw2<<<dim3(H/32, KSPLIT), 256>>>(bio, W_cat);
    k0_transpose<<<dim3(2048/32, H/32), dim3(32, 8)>>>(W_cat);
    kw3<<<dim3(H/32, 2), dim3(32, 8)>>>(W_crf);
    k_bw2fin<<<H*64/256, 256>>>();
    k1_bio_attn<<<BS/16, 256, smem1>>>(h, bio);
    k2_mma<<<dim3(H/KBN, BS/KBM), 256, SMEM_K2>>>(b_cat);
    k3_mma<<<BS/128, 256, SMEM_K3>>>(b_crf, out);
    k4_crf<<<B, 32, smem4>>>(out, labels, lens, trans, loss);
}

// round 9
// speedup vs baseline: 1.8642x; 1.0296x over previous
#include <cuda_runtime.h>
#include <cuda_bf16.h>
#include <cstdint>
#include <math.h>

// Problem constants
#define B   32
#define S   512
#define H   1024
#define T   37
#define LP  39
#define BS  (B*S)          // 16384
#define ZK2 2112           // 1024 (h) + 1024 (h*aware) + 64 (attn pad)
#define KSPLIT 8

// Scratch (device-global)
__device__ __align__(256) __nv_bfloat16 g_Zb[BS * ZK2];  // 66 MiB
__device__ __align__(256) __nv_bfloat16 g_Wt[H * ZK2];   // [n][k]  4.3 MiB
__device__ __align__(256) __nv_bfloat16 g_Yb[BS * H];    // gelu out, bf16, 32 MiB
__device__ __align__(256) __nv_bfloat16 g_W3[64 * H];    // W_crf^T padded, bf16
__device__ __align__(256) float g_BW2p[KSPLIT * T * H];  // bw2 partials, 1.2 MiB

// ===========================================================================
// helpers
// ===========================================================================
__device__ __forceinline__ uint32_t smem_u32(const void* p) {
    uint32_t a;
    asm("{ .reg .u64 t; cvta.to.shared.u64 t, %1; cvt.u32.u64 %0, t; }"
        : "=r"(a) : "l"(p));
    return a;
}
__device__ __forceinline__ void cp16(uint32_t dst, const void* src) {
    asm volatile("cp.async.cg.shared.global [%0], [%1], 16;\n" :: "r"(dst), "l"(src));
}
#define CP_COMMIT() asm volatile("cp.async.commit_group;\n" ::: "memory")
#define CP_WAIT(n)  asm volatile("cp.async.wait_group %0;\n" :: "n"(n) : "memory")

__device__ __forceinline__ float gelu(float v) {
    return 0.5f * v * (1.f + erff(v * 0.70710678118654752f));
}
__device__ __forceinline__ void ldsm4(uint32_t* r, uint32_t addr) {
    asm volatile("ldmatrix.sync.aligned.m8n8.x4.shared.b16 {%0,%1,%2,%3}, [%4];"
        : "=r"(r[0]), "=r"(r[1]), "=r"(r[2]), "=r"(r[3]) : "r"(addr));
}
__device__ __forceinline__ void mma_bf16(
    float* d, const uint32_t* a, uint32_t b0, uint32_t b1)
{
    asm volatile(
        "mma.sync.aligned.m16n8k16.row.col.f32.bf16.bf16.f32 "
        "{%0,%1,%2,%3}, {%4,%5,%6,%7}, {%8,%9}, {%0,%1,%2,%3};"
        : "+f"(d[0]), "+f"(d[1]), "+f"(d[2]), "+f"(d[3])
        : "r"(a[0]), "r"(a[1]), "r"(a[2]), "r"(a[3]), "r"(b0), "r"(b1));
}
__device__ __forceinline__ float rmax32(float x) {
    uint32_t k = __float_as_uint(x);
    k = (k & 0x80000000u) ? ~k : (k | 0x80000000u);
    k = __reduce_max_sync(0xFFFFFFFFu, k);
    return __uint_as_float((k & 0x80000000u) ? (k & 0x7FFFFFFFu) : ~k);
}
__device__ __forceinline__ uint2 pack4bf(float4 v) {
    __nv_bfloat162 p0; p0.x = __float2bfloat16(v.x); p0.y = __float2bfloat16(v.y);
    __nv_bfloat162 p1; p1.x = __float2bfloat16(v.z); p1.y = __float2bfloat16(v.w);
    uint2 r; r.x = *(uint32_t*)&p0; r.y = *(uint32_t*)&p1; return r;
}

// ---------------------------------------------------------------------------
// k_bw2: partial[by][t][n] = sum_{k in chunk} bio[t][k] * W_cat[1024+k][n]
// grid (H/32, KSPLIT): 256 blocks, 128 k-iters each.
// ---------------------------------------------------------------------------
__global__ __launch_bounds__(256) void k_bw2(
    const float* __restrict__ bio, const float* __restrict__ W)
{
    __shared__ float bioS[T * 128 + 32];    // [T][128] k-chunk of bio
    int tid = threadIdx.x;
    int k0 = blockIdx.y * 128;
    for (int i = tid; i < T * 32; i += 256) {           // 37 rows x 32 f4
        int t = i >> 5, c = i & 31;
        ((float4*)&bioS[t*128])[c] = ((const float4*)(bio + (size_t)t * H + k0))[c];
    }
    __syncthreads();

    int n = blockIdx.x * 32 + (tid & 31);
    int th = tid >> 5;
    float acc[5] = {0.f, 0.f, 0.f, 0.f, 0.f};
    #pragma unroll 4
    for (int k = 0; k < 128; k++) {
        float w = W[(size_t)(H + k0 + k) * H + n];
        #pragma unroll
        for (int j = 0; j < 5; j++) {
            int t = th + 8*j;
            float bv = (t < T) ? bioS[t*128 + k] : 0.f;
            acc[j] += bv * w;
        }
    }
    float* pp = g_BW2p + (size_t)blockIdx.y * T * H;
    #pragma unroll
    for (int j = 0; j < 5; j++) {
        int t = th + 8*j;
        if (t < T) pp[t*H + n] = acc[j];
    }
}

// ---------------------------------------------------------------------------
// kprep: merged prep work, 1D grid of 2368 blocks x 256 threads.
//   blocks [0, 2048):    g_Wt[n][k] = bf16(W_cat[src(k)][n]), k<2048
//   blocks [2048, 2112): g_W3[t][k] = bf16(W_crf[k][t]) (t>=T zero)
//   blocks [2112, 2368): g_Wt[n][2048+c] = bf16(sum_s BW2 partial) / pads
// ---------------------------------------------------------------------------
__global__ __launch_bounds__(256) void kprep(
    const float* __restrict__ W, const float* __restrict__ Wc)
{
    __shared__ float tile[32][33];
    int bid = blockIdx.x;
    int tid = threadIdx.x;
    int tx = tid & 31, ty = tid >> 5;

    if (bid < 2048) {
        int k0 = (bid & 63) * 32;      // 64 k-tiles
        int n0 = (bid >> 6) * 32;      // 32 n-tiles
        #pragma unroll
        for (int j = 0; j < 32; j += 8) {
            int k = k0 + ty + j;
            int src = (k < H) ? k : (k + H);
            tile[ty + j][tx] = W[(size_t)src * H + n0 + tx];
        }
        __syncthreads();
        #pragma unroll
        for (int j = 0; j < 32; j += 8) {
            int n = n0 + ty + j;
            g_Wt[(size_t)n * ZK2 + k0 + tx] = __float2bfloat16(tile[tx][ty + j]);
        }
    } else if (bid < 2112) {
        int b2 = bid - 2048;           // 0..63
        int k0 = (b2 & 31) * 32;       // 32 k-tiles
        int t0 = (b2 >> 5) * 32;       // 2 t-tiles
        #pragma unroll
        for (int j = 0; j < 32; j += 8) {
            int k = k0 + ty + j, t = t0 + tx;
            tile[ty + j][tx] = (t < T) ? Wc[(size_t)k * T + t] : 0.f;
        }
        __syncthreads();
        #pragma unroll
        for (int j = 0; j < 32; j += 8) {
            int t = t0 + ty + j;
            g_W3[(size_t)t * H + k0 + tx] = __float2bfloat16(tile[tx][ty + j]);
        }
    } else {
        int idx = (bid - 2112) * 256 + tid;   // 0 .. H*64-1
        int n = idx >> 6, c = idx & 63;
        float s = 0.f;
        if (c < T) {
            #pragma unroll
            for (int q = 0; q < KSPLIT; q++)
                s += g_BW2p[(size_t)q * T * H + c*H + n];
        }
        g_Wt[(size_t)n * ZK2 + 2048 + c] = __float2bfloat16(s);
    }
}

// ---------------------------------------------------------------------------
// k1: 2 rows per warp, bf16 bio tile in smem, HFMA2 bf16x2 arithmetic.
// scores -> softmax -> aware; Z = bf16[h | h*aware | attn]
// ---------------------------------------------------------------------------
__global__ __launch_bounds__(256, 2) void k1_bio_attn(
    const float* __restrict__ h, const float* __restrict__ bio)
{
    extern __shared__ __align__(16) __nv_bfloat16 bioB[];   // [T][H] bf16
    int tid = threadIdx.x;
    for (int i = tid; i < T*H/2; i += 256) {
        float2 v = ((const float2*)bio)[i];
        __nv_bfloat162 p; p.x = __float2bfloat16(v.x); p.y = __float2bfloat16(v.y);
        ((__nv_bfloat162*)bioB)[i] = p;
    }
    __syncthreads();

    int wid = tid >> 5, l = tid & 31;
    int row0 = (blockIdx.x * 8 + wid) * 2;
    int row1 = row0 + 1;
    const uint2* bB = (const uint2*)bioB;   // 4 bf16 per entry, row stride 256

    // h rows as packed bf16 (also the Z h-part payload)
    uint2 h0p[8], h1p[8];
    {
        const float4* p0 = (const float4*)(h + (size_t)row0 * H);
        const float4* p1 = (const float4*)(h + (size_t)row1 * H);
        __nv_bfloat16* zr0 = g_Zb + (size_t)row0 * ZK2;
        __nv_bfloat16* zr1 = g_Zb + (size_t)row1 * ZK2;
        #pragma unroll
        for (int j = 0; j < 8; j++) {
            h0p[j] = pack4bf(p0[j*32 + l]);
            h1p[j] = pack4bf(p1[j*32 + l]);
            *(uint2*)(zr0 + j*128 + 4*l) = h0p[j];
            *(uint2*)(zr1 + j*128 + 4*l) = h1p[j];
        }
    }

    // ---- phase A: scores via HFMA2 (partial bf16 accum, f32 reduce) ----
    float v0a = -1e30f, v0b = -1e30f, v1a = -1e30f, v1b = -1e30f;
    const __nv_bfloat162 z2 = __float2bfloat162_rn(0.f);
    for (int t = 0; t < T; t++) {
        const uint2* bt = bB + t*256;
        __nv_bfloat162 a0a = z2, a0b = z2, a1a = z2, a1b = z2;
        #pragma unroll
        for (int j = 0; j < 8; j++) {
            uint2 pk = bt[j*32 + l];
            __nv_bfloat162 b01 = *(__nv_bfloat162*)&pk.x;
            __nv_bfloat162 b23 = *(__nv_bfloat162*)&pk.y;
            a0a = __hfma2(b01, *(__nv_bfloat162*)&h0p[j].x, a0a);
            a0b = __hfma2(b23, *(__nv_bfloat162*)&h0p[j].y, a0b);
            a1a = __hfma2(b01, *(__nv_bfloat162*)&h1p[j].x, a1a);
            a1b = __hfma2(b23, *(__nv_bfloat162*)&h1p[j].y, a1b);
        }
        float2 f0 = __bfloat1622float2(a0a), f0q = __bfloat1622float2(a0b);
        float2 f1 = __bfloat1622float2(a1a), f1q = __bfloat1622float2(a1b);
        float s0 = (f0.x + f0.y) + (f0q.x + f0q.y);
        float s1 = (f1.x + f1.y) + (f1q.x + f1q.y);
        #pragma unroll
        for (int o = 16; o; o >>= 1) {
            s0 += __shfl_xor_sync(~0u, s0, o);
            s1 += __shfl_xor_sync(~0u, s1, o);
        }
        s0 *= 0.03125f; s1 *= 0.03125f;
        if (t < 32) { if (l == t)    { v0a = s0; v1a = s1; } }
        else        { if (l == t-32) { v0b = s0; v1b = s1; } }
    }

    // ---- softmax (per row, in-warp) ----
    float e0a, e0b, e1a, e1b;
    {
        float m0 = rmax32(fmaxf(v0a, (l < T-32) ? v0b : -1e30f));
        e0a = __expf(v0a - m0);
        e0b = (l < T-32) ? __expf(v0b - m0) : 0.f;
        float ss = e0a + e0b;
        #pragma unroll
        for (int o = 16; o; o >>= 1) ss += __shfl_xor_sync(~0u, ss, o);
        float inv = 1.f / ss; e0a *= inv; e0b *= inv;

        float m1 = rmax32(fmaxf(v1a, (l < T-32) ? v1b : -1e30f));
        e1a = __expf(v1a - m1);
        e1b = (l < T-32) ? __expf(v1b - m1) : 0.f;
        float s1s = e1a + e1b;
        #pragma unroll
        for (int o = 16; o; o >>= 1) s1s += __shfl_xor_sync(~0u, s1s, o);
        float inv1 = 1.f / s1s; e1a *= inv1; e1b *= inv1;
    }

    // attn columns [2048, 2112)
    {
        __nv_bfloat16* zr0 = g_Zb + (size_t)row0 * ZK2;
        __nv_bfloat16* zr1 = g_Zb + (size_t)row1 * ZK2;
        int i0 = 2*l, i1 = 2*l + 1;
        float r0lo0 = __shfl_sync(~0u, e0a, i0 & 31);
        float r0hi0 = __shfl_sync(~0u, e0b, (i0 >= 32) ? (i0 - 32) : 0);
        float r0lo1 = __shfl_sync(~0u, e0a, i1 & 31);
        float r0hi1 = __shfl_sync(~0u, e0b, (i1 >= 32) ? (i1 - 32) : 0);
        float r1lo0 = __shfl_sync(~0u, e1a, i0 & 31);
        float r1hi0 = __shfl_sync(~0u, e1b, (i0 >= 32) ? (i0 - 32) : 0);
        float r1lo1 = __shfl_sync(~0u, e1a, i1 & 31);
        float r1hi1 = __shfl_sync(~0u, e1b, (i1 >= 32) ? (i1 - 32) : 0);
        float a00 = (i0 < 32) ? r0lo0 : r0hi0; if (i0 >= T) a00 = 0.f;
        float a01 = (i1 < 32) ? r0lo1 : r0hi1; if (i1 >= T) a01 = 0.f;
        float a10 = (i0 < 32) ? r1lo0 : r1hi0; if (i0 >= T) a10 = 0.f;
        float a11 = (i1 < 32) ? r1lo1 : r1hi1; if (i1 >= T) a11 = 0.f;
        __nv_bfloat162 q0; q0.x = __float2bfloat16(a00); q0.y = __float2bfloat16(a01);
        __nv_bfloat162 q1; q1.x = __float2bfloat16(a10); q1.y = __float2bfloat16(a11);
        *(uint32_t*)(zr0 + 2048 + 2*l) = *(uint32_t*)&q0;
        *(uint32_t*)(zr1 + 2048 + 2*l) = *(uint32_t*)&q1;
    }

    // ---- phase B: aware accumulation in bf16x2 ----
    __nv_bfloat162 aw0[16], aw1[16];
    #pragma unroll
    for (int j = 0; j < 16; j++) { aw0[j] = z2; aw1[j] = z2; }
    for (int t = 0; t < T; t++) {
        float a0f = (t < 32) ? __shfl_sync(~0u, e0a, t) : __shfl_sync(~0u, e0b, t - 32);
        float a1f = (t < 32) ? __shfl_sync(~0u, e1a, t) : __shfl_sync(~0u, e1b, t - 32);
        __nv_bfloat162 a0v = __float2bfloat162_rn(a0f);
        __nv_bfloat162 a1v = __float2bfloat162_rn(a1f);
        const uint2* bt = bB + t*256;
        #pragma unroll
        for (int j = 0; j < 8; j++) {
            uint2 pk = bt[j*32 + l];
            __nv_bfloat162 b01 = *(__nv_bfloat162*)&pk.x;
            __nv_bfloat162 b23 = *(__nv_bfloat162*)&pk.y;
            aw0[2*j]   = __hfma2(b01, a0v, aw0[2*j]);
            aw0[2*j+1] = __hfma2(b23, a0v, aw0[2*j+1]);
            aw1[2*j]   = __hfma2(b01, a1v, aw1[2*j]);
            aw1[2*j+1] = __hfma2(b23, a1v, aw1[2*j+1]);
        }
    }

    // product h * aware (bf16x2 mul), store
    {
        __nv_bfloat16* zr0 = g_Zb + (size_t)row0 * ZK2;
        __nv_bfloat16* zr1 = g_Zb + (size_t)row1 * ZK2;
        #pragma unroll
        for (int j = 0; j < 8; j++) {
            __nv_bfloat162 p0x = __hmul2(aw0[2*j],   *(__nv_bfloat162*)&h0p[j].x);
            __nv_bfloat162 p0y = __hmul2(aw0[2*j+1], *(__nv_bfloat162*)&h0p[j].y);
            uint2 pk0; pk0.x = *(uint32_t*)&p0x; pk0.y = *(uint32_t*)&p0y;
            *(uint2*)(zr0 + 1024 + j*128 + 4*l) = pk0;
            __nv_bfloat162 p1x = __hmul2(aw1[2*j],   *(__nv_bfloat162*)&h1p[j].x);
            __nv_bfloat162 p1y = __hmul2(aw1[2*j+1], *(__nv_bfloat162*)&h1p[j].y);
            uint2 pk1; pk1.x = *(uint32_t*)&p1x; pk1.y = *(uint32_t*)&p1y;
            *(uint2*)(zr1 + 1024 + j*128 + 4*l) = pk1;
        }
    }
}

// ---------------------------------------------------------------------------
// k2: Yb = bf16(gelu(Z @ Wt^T + bc))  bf16 mma, BM=128 BN=128 BK=64,
// 3-stage cp.async, SINGLE sync/iter: wait(1) -> sync -> compute -> load.
// ---------------------------------------------------------------------------
#define KBM 128
#define KBN 128
#define KBK 64
#define NKI (ZK2/KBK)            // 33
#define STG (KBM*128 + KBN*128)  // 32768 bytes
#define SMEM_K2 (3*STG)          // 98304

__device__ __forceinline__ void k2_load_stage(
    uint32_t sb, int tid, int j, const char* Zb, const char* Wb)
{
    uint32_t base = sb + (j % 3) * STG;
    int kb = j * 128;
    #pragma unroll
    for (int q = 0; q < 8; q++) {
        int idx = tid + 256*q;
        if (q < 4) {
            int m = idx >> 3, c = idx & 7;
            cp16(base + ((m*128 + c*16) ^ ((m & 7) << 4)),
                 Zb + (size_t)m * (ZK2*2) + kb + c*16);
        } else {
            int ci = idx - 1024;
            int n = ci >> 3, c = ci & 7;
            cp16(base + 16384 + ((n*128 + c*16) ^ ((n & 7) << 4)),
                 Wb + (size_t)n * (ZK2*2) + kb + c*16);
        }
    }
}

__global__ __launch_bounds__(256, 2) void k2_mma(const float* __restrict__ bc)
{
    extern __shared__ __align__(16) char smem[];
    uint32_t sb = smem_u32(smem);
    int tid = threadIdx.x, lane = tid & 31, wid = tid >> 5;
    int wm = wid & 3, wn = wid >> 2;
    int row0 = blockIdx.y * KBM, n0 = blockIdx.x * KBN;

    const char* Zb = (const char*)g_Zb + (size_t)row0 * (ZK2*2);
    const char* Wb = (const char*)g_Wt + (size_t)n0   * (ZK2*2);

    float acc[2][8][4];
    #pragma unroll
    for (int mt = 0; mt < 2; mt++)
        #pragma unroll
        for (int nt = 0; nt < 8; nt++)
            #pragma unroll
            for (int q = 0; q < 4; q++) acc[mt][nt][q] = 0.f;

    k2_load_stage(sb, tid, 0, Zb, Wb); CP_COMMIT();
    k2_load_stage(sb, tid, 1, Zb, Wb); CP_COMMIT();

    int r15 = lane & 15;
    int hb  = (lane >> 4) << 4;

    for (int i = 0; i < NKI; i++) {
        CP_WAIT(1);
        __syncthreads();

        uint32_t Ab = sb + (i % 3) * STG;
        uint32_t Bb = Ab + 16384;
        #pragma unroll
        for (int kk = 0; kk < 4; kk++) {
            int kbyte = kk*32 + hb;
            uint32_t a[2][4];
            #pragma unroll
            for (int mt = 0; mt < 2; mt++) {
                int rr = wm*32 + mt*16 + r15;
                ldsm4(a[mt], Ab + rr*128 + (kbyte ^ ((rr & 7) << 4)));
            }
            #pragma unroll
            for (int ntp = 0; ntp < 4; ntp++) {
                int nr = wn*64 + ntp*16 + r15;
                uint32_t b[4];
                ldsm4(b, Bb + nr*128 + (kbyte ^ ((nr & 7) << 4)));
                #pragma unroll
                for (int mt = 0; mt < 2; mt++) {
                    mma_bf16(acc[mt][2*ntp],   a[mt], b[0], b[2]);
                    mma_bf16(acc[mt][2*ntp+1], a[mt], b[1], b[3]);
                }
            }
        }

        int j = i + 2;
        if (j < NKI) k2_load_stage(sb, tid, j, Zb, Wb);
        CP_COMMIT();
    }

    int g = lane >> 2, t4 = lane & 3;
    #pragma unroll
    for (int mt = 0; mt < 2; mt++) {
        #pragma unroll
        for (int nt = 0; nt < 8; nt++) {
            int r0 = row0 + wm*32 + mt*16 + g;
            int c  = n0 + wn*64 + nt*8 + 2*t4;
            float b0v = __ldg(bc + c), b1v = __ldg(bc + c + 1);
            __nv_bfloat162 o0, o1;
            o0.x = __float2bfloat16(gelu(acc[mt][nt][0] + b0v));
            o0.y = __float2bfloat16(gelu(acc[mt][nt][1] + b1v));
            o1.x = __float2bfloat16(gelu(acc[mt][nt][2] + b0v));
            o1.y = __float2bfloat16(gelu(acc[mt][nt][3] + b1v));
            *(uint32_t*)(g_Yb + (size_t)r0 * H + c) = *(uint32_t*)&o0;
            *(uint32_t*)(g_Yb + (size_t)(r0 + 8) * H + c) = *(uint32_t*)&o1;
        }
    }
}

// ---------------------------------------------------------------------------
// k3: logits = Yb @ W3^T + b_crf -> ner_scores (+ pads), via bf16 mma.
// BM=128, BN=64, BK=64, 3-stage, single sync/iter.
// ---------------------------------------------------------------------------
#define STG3 (128*128 + 64*128)   // 24576 bytes
#define SMEM_K3 (3*STG3)          // 73728
#define NKI3 (H/64)               // 16

__device__ __forceinline__ void k3_load_stage(
    uint32_t sb, int tid, int j, const char* Yb)
{
    uint32_t base = sb + (j % 3) * STG3;
    int kb = j * 128;
    #pragma unroll
    for (int q = 0; q < 6; q++) {
        int idx = tid + 256*q;
        if (q < 4) {
            int m = idx >> 3, c = idx & 7;
            cp16(base + ((m*128 + c*16) ^ ((m & 7) << 4)),
                 Yb + (size_t)m * (H*2) + kb + c*16);
        } else {
            int ci = idx - 1024;
            int n = ci >> 3, c = ci & 7;
            cp16(base + 16384 + ((n*128 + c*16) ^ ((n & 7) << 4)),
                 (const char*)g_W3 + (size_t)n * (H*2) + kb + c*16);
        }
    }
}

__global__ __launch_bounds__(256, 2) void k3_mma(
    const float* __restrict__ bcrf, float* __restrict__ out)
{
    extern __shared__ __align__(16) char smem[];
    uint32_t sb = smem_u32(smem);
    int tid = threadIdx.x, lane = tid & 31, wid = tid >> 5;
    int wm = wid & 3, wn = wid >> 2;          // 4 x 2
    int row0 = blockIdx.x * 128;

    const char* Yb = (const char*)g_Yb + (size_t)row0 * (H*2);

    float acc[2][4][4];
    #pragma unroll
    for (int mt = 0; mt < 2; mt++)
        #pragma unroll
        for (int nt = 0; nt < 4; nt++)
            #pragma unroll
            for (int q = 0; q < 4; q++) acc[mt][nt][q] = 0.f;

    k3_load_stage(sb, tid, 0, Yb); CP_COMMIT();
    k3_load_stage(sb, tid, 1, Yb); CP_COMMIT();

    int r15 = lane & 15;
    int hb  = (lane >> 4) << 4;

    for (int i = 0; i < NKI3; i++) {
        CP_WAIT(1);
        __syncthreads();

        uint32_t Ab = sb + (i % 3) * STG3;
        uint32_t Bb = Ab + 16384;
        #pragma unroll
        for (int kk = 0; kk < 4; kk++) {
            int kbyte = kk*32 + hb;
            uint32_t a[2][4];
            #pragma unroll
            for (int mt = 0; mt < 2; mt++) {
                int rr = wm*32 + mt*16 + r15;
                ldsm4(a[mt], Ab + rr*128 + (kbyte ^ ((rr & 7) << 4)));
            }
            #pragma unroll
            for (int np = 0; np < 2; np++) {
                int nr = wn*32 + np*16 + r15;
                uint32_t b[4];
                ldsm4(b, Bb + nr*128 + (kbyte ^ ((nr & 7) << 4)));
                #pragma unroll
                for (int mt = 0; mt < 2; mt++) {
                    mma_bf16(acc[mt][2*np],   a[mt], b[0], b[2]);
                    mma_bf16(acc[mt][2*np+1], a[mt], b[1], b[3]);
                }
            }
        }

        int j = i + 2;
        if (j < NKI3) k3_load_stage(sb, tid, j, Yb);
        CP_COMMIT();
    }

    int g = lane >> 2, t4 = lane & 3;
    #pragma unroll
    for (int mt = 0; mt < 2; mt++) {
        int r = row0 + wm*32 + mt*16 + g;
        #pragma unroll
        for (int nt = 0; nt < 4; nt++) {
            int c0 = wn*32 + nt*8 + 2*t4, c1 = c0 + 1;
            if (c0 < T) {
                float bv = __ldg(bcrf + c0);
                out[(size_t)r*LP + c0]     = acc[mt][nt][0] + bv;
                out[(size_t)(r+8)*LP + c0] = acc[mt][nt][2] + bv;
            }
            if (c1 < T) {
                float bv = __ldg(bcrf + c1);
                out[(size_t)r*LP + c1]     = acc[mt][nt][1] + bv;
                out[(size_t)(r+8)*LP + c1] = acc[mt][nt][3] + bv;
            }
        }
        if (wn == 1 && t4 == 0) {
            out[(size_t)r*LP + 37] = -10000.f;  out[(size_t)r*LP + 38] = -10000.f;
            out[(size_t)(r+8)*LP + 37] = -10000.f; out[(size_t)(r+8)*LP + 38] = -10000.f;
        }
    }
}

// ---------------------------------------------------------------------------
// k4: CRF loglik. One warp per batch; lagged-shift LSE scan (exact:
// shift sigma_t = rmax(a_{t-2}) -- LSE is shift-invariant; the REDUX
// runs off the critical path, overlapped with the next step's dot).
// ---------------------------------------------------------------------------
__global__ __launch_bounds__(32) void k4_crf(
    const float* __restrict__ scores, const int* __restrict__ labels,
    const int* __restrict__ lens, const float* __restrict__ trans,
    float* __restrict__ loss)
{
    extern __shared__ float sc[];   // S*LP floats
    int b = blockIdx.x;
    int lane = threadIdx.x;
    int len = lens[b];
    const int* lab = labels + b*S;

    {
        uint32_t sbase = smem_u32(sc);
        const float4* src = (const float4*)(scores + (size_t)b * S * LP);
        for (int i = lane; i < S*LP/4; i += 32)
            cp16(sbase + i*16, src + i);
        CP_COMMIT();
        CP_WAIT(0);
        __syncwarp();
    }

    float ET0[LP], ET1[LP], maxT0 = -1e30f, maxT1 = -1e30f;
    {
        const float* tr = trans + lane*LP;
        #pragma unroll
        for (int f = 0; f < LP; f++) maxT0 = fmaxf(maxT0, tr[f]);
        #pragma unroll
        for (int f = 0; f < LP; f++) ET0[f] = __expf(tr[f] - maxT0);
    }
    if (lane < LP-32) {
        const float* tr = trans + (32+lane)*LP;
        #pragma unroll
        for (int f = 0; f < LP; f++) maxT1 = fmaxf(maxT1, tr[f]);
        #pragma unroll
        for (int f = 0; f < LP; f++) ET1[f] = __expf(tr[f] - maxT1);
    }

    float g = 0.f;
    for (int s2 = lane; s2 < len; s2 += 32) g += sc[s2*LP + lab[s2]];
    for (int i = lane; i <= len; i += 32) {
        int frm = (i == 0)   ? T       : lab[i-1];
        int to  = (i == len) ? (T + 1) : lab[i];
        g += trans[to*LP + frm];
    }
    #pragma unroll
    for (int o = 16; o; o >>= 1) g += __shfl_xor_sync(~0u, g, o);

    float a0 = -100.f;
    float a1 = (lane == (T - 32)) ? 0.f : -100.f;

    // lagged shifts: s_cur used this step, s_next used next step.
    // init: max(alpha0) = 0 -> both 0.
    float s_cur = 0.f, s_next = 0.f;

    for (int t = 0; t < len; t++) {
        float e0 = __expf(a0 - s_cur);
        float e1 = (lane < LP-32) ? __expf(a1 - s_cur) : 0.f;
        float s0a = 0.f, s0b = 0.f, s1a = 0.f, s1b = 0.f;
        #pragma unroll
        for (int f = 0; f < 32; f += 2) {
            float ea = __shfl_sync(~0u, e0, f);
            float eb = __shfl_sync(~0u, e0, f+1);
            s0a += ea*ET0[f];   s0b += eb*ET0[f+1];
            s1a += ea*ET1[f];   s1b += eb*ET1[f+1];
        }
        #pragma unroll
        for (int f = 0; f < LP-32; f++) {
            float ea = __shfl_sync(~0u, e1, f);
            s0a += ea*ET0[32+f];
            s1a += ea*ET1[32+f];
        }
        a0 = sc[t*LP + lane] + s_cur + maxT0 + __logf(s0a + s0b);
        if (lane < LP-32)
            a1 = sc[t*LP + 32 + lane] + s_cur + maxT1 + __logf(s1a + s1b);
        // off-critical-path: shift for step t+2
        float m = rmax32(fmaxf(a0, (lane < LP-32) ? a1 : -1e30f));
        s_cur = s_next;
        s_next = m;
    }

    a0 += trans[(T+1)*LP + lane];
    if (lane < LP-32) a1 += trans[(T+1)*LP + 32 + lane];
    float v = rmax32(fmaxf(a0, (lane < LP-32) ? a1 : -1e30f));
    float e = __expf(a0 - v) + ((lane < LP-32) ? __expf(a1 - v) : 0.f);
    #pragma unroll
    for (int o = 16; o; o >>= 1) e += __shfl_xor_sync(~0u, e, o);
    if (lane == 0) loss[b] = g - (v + logf(e));
}

// ---------------------------------------------------------------------------
extern "C" void kernel_launch(void* const* d_in, const int* in_sizes, int n_in,
                              void* d_out, int out_size)
{
    const float* h      = (const float*)d_in[0];
    const int*   lens   = (const int*)d_in[2];
    const int*   labels = (const int*)d_in[3];
    const float* bio    = (const float*)d_in[4];
    const float* W_cat  = (const float*)d_in[5];
    const float* b_cat  = (const float*)d_in[6];
    const float* W_crf  = (const float*)d_in[7];
    const float* b_crf  = (const float*)d_in[8];
    const float* trans  = (const float*)d_in[9];

    float* out = (float*)d_out;            // ner_scores [B,S,LP] then loss [B]
    float* loss = out + (size_t)B * S * LP;

    size_t smem1  = (size_t)(T*H) * sizeof(__nv_bfloat16);  // 75776
    size_t smem4  = (size_t)(S*LP) * sizeof(float);         // 79872

    static int attr_done = 0;
    if (!attr_done) {
        cudaFuncSetAttribute(k1_bio_attn, cudaFuncAttributeMaxDynamicSharedMemorySize, (int)smem1);
        cudaFuncSetAttribute(k2_mma,      cudaFuncAttributeMaxDynamicSharedMemorySize, SMEM_K2);
        cudaFuncSetAttribute(k3_mma,      cudaFuncAttributeMaxDynamicSharedMemorySize, SMEM_K3);
        cudaFuncSetAttribute(k4_crf,      cudaFuncAttributeMaxDynamicSharedMemorySize, (int)smem4);
        attr_done = 1;
    }

    // order chosen so k2 is the 4th launch (profiler capture slot)
    k1_bio_attn<<<BS/16, 256, smem1>>>(h, bio);
    k_bw2<<<dim3(H/32, KSPLIT), 256>>>(bio, W_cat);
    kprep<<<2368, 256>>>(W_cat, W_crf);
    k2_mma<<<dim3(H/KBN, BS/KBM), 256, SMEM_K2>>>(b_cat);
    k3_mma<<<BS/128, 256, SMEM_K3>>>(b_crf, out);
    k4_crf<<<B, 32, smem4>>>(out, labels, lens, trans, loss);
}